// round 12
// baseline (speedup 1.0000x reference)
#include <cuda_runtime.h>
#include <cuda_bf16.h>
#include <cstdint>
#include <cstddef>

#define BB 8
#define CC 512
#define NN 2304
#define MD 128
#define K3F 384     // 3*MD  packed K (score operands, out-conv K)
#define K3C 1536    // 3*CC  packed K (input conv K)
#define NTILE 18    // NN / 128

typedef __nv_bfloat16 bf16;

// ---- scratch --------------------------------------------------------------
static __device__ bf16  d_Ehi [(size_t)BB * NN * NN];   // exp(alpha*S) hi [b][j][n]
static __device__ bf16  d_Elo [(size_t)BB * NN * NN];   // exp(alpha*S) lo
static __device__ float d_ps  [(size_t)BB * NTILE * NN];
static __device__ float d_inv [BB * NN];
static __device__ bf16  d_xT  [(size_t)BB * NN * K3C];  // x^T packed (hi,hi,lo)
static __device__ bf16  d_xvT [(size_t)BB * NN * K3C];
static __device__ bf16  d_xhT [(size_t)BB * NN * K3C];
static __device__ bf16  d_faT [(size_t)BB * NN * K3F];
static __device__ bf16  d_fvT [(size_t)BB * NN * K3F];
static __device__ bf16  d_fhT [(size_t)BB * NN * K3F];
static __device__ bf16  d_Wap  [MD * K3C];
static __device__ bf16  d_Wvp  [MD * K3C];
static __device__ bf16  d_Wgavp[MD * K3C];
static __device__ bf16  d_Wgahp[MD * K3C];
static __device__ bf16  d_Wfavp[CC * K3F];
static __device__ bf16  d_Wfahp[CC * K3F];
static __device__ float d_gav [(size_t)BB * MD * NN];   // fp32 g (pre-inv)
static __device__ float d_gah [(size_t)BB * MD * NN];
static __device__ bf16  d_ghi [(size_t)BB * MD * NN];   // split(g*inv), per pass
static __device__ bf16  d_glo [(size_t)BB * MD * NN];
static __device__ bf16  d_OmT [(size_t)BB * NN * K3F];  // om^T packed (hi,hi,lo)

__device__ __forceinline__ uint32_t smem_u32(const void* p) {
    uint32_t a;
    asm("{ .reg .u64 t; cvta.to.shared.u64 t, %1; cvt.u32.u64 %0, t; }" : "=r"(a) : "l"(p));
    return a;
}

// 128-row x 128-byte bf16 tile -> smem with SW128 swizzle
__device__ __forceinline__ void tile_ld(uint32_t sdst, const bf16* __restrict__ g,
                                        int ld, int tid) {
#pragma unroll
    for (int it = 0; it < 4; ++it) {
        int s = tid + it * 256;
        int r = s >> 3, c = s & 7;
        uint32_t o = (uint32_t)(r * 128 + c * 16);
        o ^= (o >> 3) & 0x70;
        asm volatile("cp.async.cg.shared.global [%0], [%1], 16;"
                     :: "r"(sdst + o), "l"(g + (size_t)r * ld + c * 8) : "memory");
    }
}

#define LDSM4(d, a)                                                          \
    asm volatile("ldmatrix.sync.aligned.m8n8.x4.shared.b16 {%0,%1,%2,%3}, [%4];" \
        : "=r"((d)[0]), "=r"((d)[1]), "=r"((d)[2]), "=r"((d)[3]) : "r"(a))
#define MMA(ac, af, b0, b1)                                                  \
    asm volatile("mma.sync.aligned.m16n8k16.row.col.f32.bf16.bf16.f32 "      \
        "{%0,%1,%2,%3}, {%4,%5,%6,%7}, {%8,%9}, {%0,%1,%2,%3};"              \
        : "+f"((ac)[0]), "+f"((ac)[1]), "+f"((ac)[2]), "+f"((ac)[3])         \
        : "r"((af)[0]), "r"((af)[1]), "r"((af)[2]), "r"((af)[3]),            \
          "r"(b0), "r"(b1))

// ---------------------------------------------------------------------------
// Generic conv HMMA: acc[m,n] = Aw[m,:].Bx[n,:] over packed K3.
// EPI 0: BN-ReLU, write fT packed [n, K3F] (PAT0: hi,hi,lo / PAT1: hi,lo,hi)
// EPI 1: +bias -> fp32 Cf [m, NN]
// EPI 2: +bias + resid -> fp32 Cf [m, NN]
// ---------------------------------------------------------------------------
template<int EPI, int PAT>
__global__ void __launch_bounds__(256, 1)
hmma_conv(const bf16* __restrict__ Aw,                 // [Ma, K3] batch-shared
          const bf16* __restrict__ Bx, size_t sB,      // [N, K3] per batch
          int K3,
          float* __restrict__ Cf, size_t sC,
          bf16* __restrict__ O1, size_t sO,
          const float* __restrict__ bias,
          const float* __restrict__ gam, const float* __restrict__ bet,
          const float* __restrict__ resid, size_t sR)
{
    extern __shared__ char smem[];
    const uint32_t sb = smem_u32(smem);
    const int tid = threadIdx.x, wid = tid >> 5, lane = tid & 31;
    const int b = blockIdx.z;
    const int m0 = blockIdx.y * 128, n0 = blockIdx.x * 128;
    Aw += (size_t)m0 * K3;
    Bx += (size_t)b * sB + (size_t)n0 * K3;
    if (EPI == 0) { O1 += (size_t)b * sO; }
    else          { Cf += (size_t)b * sC; if (EPI == 2) resid += (size_t)b * sR; }

    const int mW = (wid & 1) * 64, nW = (wid >> 1) * 32;
    float acc[4][4][4];
#pragma unroll
    for (int i = 0; i < 4; ++i)
#pragma unroll
        for (int j = 0; j < 4; ++j)
#pragma unroll
            for (int k = 0; k < 4; ++k) acc[i][j][k] = 0.f;

    const uint32_t oA[2] = { sb, sb + 32768 };
    const uint32_t oB[2] = { sb + 16384, sb + 49152 };
    tile_ld(oA[0], Aw, K3, tid);
    tile_ld(oB[0], Bx, K3, tid);
    asm volatile("cp.async.commit_group;" ::: "memory");

    const int li8 = lane & 7, sel = lane >> 3;
    const int nC = K3 >> 6;
    int buf = 0;
    for (int c = 0; c < nC; ++c) {
        if (c + 1 < nC) {
            tile_ld(oA[buf ^ 1], Aw + (size_t)(c + 1) * 64, K3, tid);
            tile_ld(oB[buf ^ 1], Bx + (size_t)(c + 1) * 64, K3, tid);
            asm volatile("cp.async.commit_group;" ::: "memory");
            asm volatile("cp.async.wait_group 1;" ::: "memory");
        } else {
            asm volatile("cp.async.wait_group 0;" ::: "memory");
        }
        __syncthreads();
        const uint32_t ab = oA[buf], bb = oB[buf];
#pragma unroll
        for (int ks = 0; ks < 4; ++ks) {
            const int kb = ks * 32;
            uint32_t af[4][4], bfr[2][4];
#pragma unroll
            for (int mi = 0; mi < 4; ++mi) {
                int row = mW + mi * 16 + li8 + (sel & 1) * 8;
                uint32_t o = (uint32_t)(row * 128 + kb + (sel >> 1) * 16);
                o ^= (o >> 3) & 0x70;
                LDSM4(af[mi], ab + o);
            }
#pragma unroll
            for (int nq = 0; nq < 2; ++nq) {
                int row = nW + nq * 16 + li8 + (sel >> 1) * 8;
                uint32_t o = (uint32_t)(row * 128 + kb + (sel & 1) * 16);
                o ^= (o >> 3) & 0x70;
                LDSM4(bfr[nq], bb + o);
            }
#pragma unroll
            for (int mi = 0; mi < 4; ++mi)
#pragma unroll
                for (int ni = 0; ni < 4; ++ni)
                    MMA(acc[mi][ni], af[mi],
                        bfr[ni >> 1][(ni & 1) * 2], bfr[ni >> 1][(ni & 1) * 2 + 1]);
        }
        __syncthreads();
        buf ^= 1;
    }

    const int g8 = lane >> 2, tg = lane & 3;
    if (EPI == 0) {
        float (*stage)[129] = (float(*)[129])smem;
        const float rs = rsqrtf(1.f + 1e-5f);
#pragma unroll
        for (int mi = 0; mi < 4; ++mi) {
            const int r0 = mW + mi * 16 + g8, r1 = r0 + 8;
            const float s0 = gam[r0] * rs, b0 = fmaf(bias[r0], s0, bet[r0]);
            const float s1 = gam[r1] * rs, b1 = fmaf(bias[r1], s1, bet[r1]);
#pragma unroll
            for (int ni = 0; ni < 4; ++ni) {
                const int c = nW + ni * 8 + tg * 2;
                stage[c][r0]     = fmaxf(fmaf(acc[mi][ni][0], s0, b0), 0.f);
                stage[c + 1][r0] = fmaxf(fmaf(acc[mi][ni][1], s0, b0), 0.f);
                stage[c][r1]     = fmaxf(fmaf(acc[mi][ni][2], s1, b1), 0.f);
                stage[c + 1][r1] = fmaxf(fmaf(acc[mi][ni][3], s1, b1), 0.f);
            }
        }
        __syncthreads();
        for (int e = tid; e < 16384; e += 256) {
            int nn = e >> 7, m = e & 127;
            float v = stage[nn][m];
            bf16 h = __float2bfloat16(v);
            bf16 l = __float2bfloat16(v - __bfloat162float(h));
            size_t o = (size_t)(n0 + nn) * K3F;
            O1[o + m]       = h;
            O1[o + 128 + m] = PAT ? l : h;
            O1[o + 256 + m] = PAT ? h : l;
        }
    } else {
#pragma unroll
        for (int mi = 0; mi < 4; ++mi) {
            const int r0 = m0 + mW + mi * 16 + g8;
            const float bs0 = bias[r0], bs1 = bias[r0 + 8];
#pragma unroll
            for (int ni = 0; ni < 4; ++ni) {
                const int n = n0 + nW + ni * 8 + tg * 2;
                const size_t i0r = (size_t)r0 * NN + n, i1r = (size_t)(r0 + 8) * NN + n;
                float a0 = acc[mi][ni][0] + bs0, a1 = acc[mi][ni][1] + bs0;
                float a2 = acc[mi][ni][2] + bs1, a3 = acc[mi][ni][3] + bs1;
                if (EPI == 2) {
                    float2 rs0 = *(const float2*)&resid[i0r];
                    float2 rs1 = *(const float2*)&resid[i1r];
                    a0 += rs0.x; a1 += rs0.y; a2 += rs1.x; a3 += rs1.y;
                }
                *(float2*)&Cf[i0r] = make_float2(a0, a1);
                *(float2*)&Cf[i1r] = make_float2(a2, a3);
            }
        }
    }
}

// ---------------------------------------------------------------------------
// Score: E[j,n] = exp(alpha * <faT[j,:], fqT[n,:]>), packed K=384.
// Writes Ehi/Elo bf16 + per-tile column partial sums PS.
// ---------------------------------------------------------------------------
__global__ void __launch_bounds__(256, 1)
hmma_score(const bf16* __restrict__ A, const bf16* __restrict__ B, size_t sF,
           bf16* __restrict__ Ehi, bf16* __restrict__ Elo,
           float* __restrict__ PS, float alpha)
{
    extern __shared__ char smem[];
    const uint32_t sb = smem_u32(smem);
    const int tid = threadIdx.x, wid = tid >> 5, lane = tid & 31;
    const int b = blockIdx.z;
    const int i0 = blockIdx.y * 128, j0 = blockIdx.x * 128;
    A += (size_t)b * sF + (size_t)i0 * K3F;
    B += (size_t)b * sF + (size_t)j0 * K3F;
    Ehi += (size_t)b * NN * NN;
    Elo += (size_t)b * NN * NN;

    const int mW = (wid & 1) * 64, nW = (wid >> 1) * 32;
    float acc[4][4][4];
#pragma unroll
    for (int i = 0; i < 4; ++i)
#pragma unroll
        for (int j = 0; j < 4; ++j)
#pragma unroll
            for (int k = 0; k < 4; ++k) acc[i][j][k] = 0.f;

    const uint32_t oA[2] = { sb, sb + 32768 };
    const uint32_t oB[2] = { sb + 16384, sb + 49152 };
    tile_ld(oA[0], A, K3F, tid);
    tile_ld(oB[0], B, K3F, tid);
    asm volatile("cp.async.commit_group;" ::: "memory");

    const int li8 = lane & 7, sel = lane >> 3;
    int buf = 0;
    for (int c = 0; c < 6; ++c) {
        if (c + 1 < 6) {
            tile_ld(oA[buf ^ 1], A + (size_t)(c + 1) * 64, K3F, tid);
            tile_ld(oB[buf ^ 1], B + (size_t)(c + 1) * 64, K3F, tid);
            asm volatile("cp.async.commit_group;" ::: "memory");
            asm volatile("cp.async.wait_group 1;" ::: "memory");
        } else {
            asm volatile("cp.async.wait_group 0;" ::: "memory");
        }
        __syncthreads();
        const uint32_t ab = oA[buf], bb = oB[buf];
#pragma unroll
        for (int ks = 0; ks < 4; ++ks) {
            const int kb = ks * 32;
            uint32_t af[4][4], bfr[2][4];
#pragma unroll
            for (int mi = 0; mi < 4; ++mi) {
                int row = mW + mi * 16 + li8 + (sel & 1) * 8;
                uint32_t o = (uint32_t)(row * 128 + kb + (sel >> 1) * 16);
                o ^= (o >> 3) & 0x70;
                LDSM4(af[mi], ab + o);
            }
#pragma unroll
            for (int nq = 0; nq < 2; ++nq) {
                int row = nW + nq * 16 + li8 + (sel >> 1) * 8;
                uint32_t o = (uint32_t)(row * 128 + kb + (sel & 1) * 16);
                o ^= (o >> 3) & 0x70;
                LDSM4(bfr[nq], bb + o);
            }
#pragma unroll
            for (int mi = 0; mi < 4; ++mi)
#pragma unroll
                for (int ni = 0; ni < 4; ++ni)
                    MMA(acc[mi][ni], af[mi],
                        bfr[ni >> 1][(ni & 1) * 2], bfr[ni >> 1][(ni & 1) * 2 + 1]);
        }
        __syncthreads();
        buf ^= 1;
    }

    const int g8 = lane >> 2, tg = lane & 3;
    float ev[4][4][4];
#pragma unroll
    for (int mi = 0; mi < 4; ++mi)
#pragma unroll
        for (int ni = 0; ni < 4; ++ni)
#pragma unroll
            for (int k = 0; k < 4; ++k)
                ev[mi][ni][k] = __expf(acc[mi][ni][k] * alpha);
#pragma unroll
    for (int mi = 0; mi < 4; ++mi)
#pragma unroll
        for (int ni = 0; ni < 4; ++ni) {
            const int r  = i0 + mW + mi * 16 + g8;
            const int cN = j0 + nW + ni * 8 + tg * 2;
            __nv_bfloat162 h01 = __floats2bfloat162_rn(ev[mi][ni][0], ev[mi][ni][1]);
            __nv_bfloat162 h23 = __floats2bfloat162_rn(ev[mi][ni][2], ev[mi][ni][3]);
            float2 f01 = __bfloat1622float2(h01);
            float2 f23 = __bfloat1622float2(h23);
            __nv_bfloat162 l01 = __floats2bfloat162_rn(ev[mi][ni][0] - f01.x,
                                                       ev[mi][ni][1] - f01.y);
            __nv_bfloat162 l23 = __floats2bfloat162_rn(ev[mi][ni][2] - f23.x,
                                                       ev[mi][ni][3] - f23.y);
            *(__nv_bfloat162*)&Ehi[(size_t)r * NN + cN]       = h01;
            *(__nv_bfloat162*)&Elo[(size_t)r * NN + cN]       = l01;
            *(__nv_bfloat162*)&Ehi[(size_t)(r + 8) * NN + cN] = h23;
            *(__nv_bfloat162*)&Elo[(size_t)(r + 8) * NN + cN] = l23;
        }
    float cs[8];
#pragma unroll
    for (int ni = 0; ni < 4; ++ni)
#pragma unroll
        for (int par = 0; par < 2; ++par) {
            float s = 0.f;
#pragma unroll
            for (int mi = 0; mi < 4; ++mi)
                s += ev[mi][ni][par] + ev[mi][ni][2 + par];
            cs[ni * 2 + par] = s;
        }
#pragma unroll
    for (int o = 4; o <= 16; o <<= 1)
#pragma unroll
        for (int e = 0; e < 8; ++e)
            cs[e] += __shfl_xor_sync(0xffffffffu, cs[e], o);
    float* sP = (float*)smem;
    if (g8 == 0) {
#pragma unroll
        for (int ni = 0; ni < 4; ++ni)
#pragma unroll
            for (int par = 0; par < 2; ++par)
                sP[(wid & 1) * 128 + nW + ni * 8 + tg * 2 + par] = cs[ni * 2 + par];
    }
    __syncthreads();
    if (tid < 128)
        PS[((size_t)(b * NTILE + blockIdx.y)) * NN + j0 + tid] = sP[tid] + sP[128 + tid];
}

// inv[b][n] = 1 / sum_t PS[b][t][n]
__global__ void __launch_bounds__(256)
finalize_inv(const float* __restrict__ PS, float* __restrict__ inv)
{
    const int b = blockIdx.z;
    const int n = blockIdx.x * 256 + threadIdx.x;
    float s = 0.f;
#pragma unroll
    for (int t = 0; t < NTILE; ++t)
        s += PS[((size_t)(b * NTILE + t)) * NN + n];
    inv[b * NN + n] = 1.f / s;
}

// ghi/glo = split(g * inv[n]), vectorized x2
__global__ void __launch_bounds__(256)
gscale(const float* __restrict__ g, const float* __restrict__ inv,
       bf16* __restrict__ Ghi, bf16* __restrict__ Glo)
{
    const int b = blockIdx.z;
    const size_t i2 = ((size_t)blockIdx.x * 256 + threadIdx.x) * 2;
    const size_t base = (size_t)b * MD * NN;
    const int n = (int)(i2 % NN);
    float2 v = *(const float2*)&g[base + i2];
    float2 iv = *(const float2*)&inv[b * NN + n];
    v.x *= iv.x; v.y *= iv.y;
    __nv_bfloat162 h = __floats2bfloat162_rn(v.x, v.y);
    float2 f = __bfloat1622float2(h);
    __nv_bfloat162 l = __floats2bfloat162_rn(v.x - f.x, v.y - f.y);
    *(__nv_bfloat162*)&Ghi[base + i2] = h;
    *(__nv_bfloat162*)&Glo[base + i2] = l;
}

// ---------------------------------------------------------------------------
// Apply: om[m,j] = sum_n g'[m,n] * E[j,n]; 3-term bf16 (ghi*Ehi + ghi*Elo +
// glo*Ehi), K=2304, conv-style 2-deep pipeline, all-bf16 tiles.
// Emits OmT packed [j, K3F] (hi,hi,lo).
// ---------------------------------------------------------------------------
__global__ void __launch_bounds__(256, 1)
apply_fused(const bf16* __restrict__ Ghi, const bf16* __restrict__ Glo,
            const bf16* __restrict__ Ehi, const bf16* __restrict__ Elo,
            bf16* __restrict__ OmT)
{
    extern __shared__ char smem[];
    const uint32_t sb = smem_u32(smem);
    const int tid = threadIdx.x, wid = tid >> 5, lane = tid & 31;
    const int b = blockIdx.z;
    const int j0 = blockIdx.x * 128;
    Ghi += (size_t)b * MD * NN;
    Glo += (size_t)b * MD * NN;
    Ehi += (size_t)b * NN * NN + (size_t)j0 * NN;
    Elo += (size_t)b * NN * NN + (size_t)j0 * NN;
    OmT += (size_t)b * NN * K3F;

    const int mW = (wid & 1) * 64, nW = (wid >> 1) * 32;
    float acc[4][4][4];
#pragma unroll
    for (int i = 0; i < 4; ++i)
#pragma unroll
        for (int j = 0; j < 4; ++j)
#pragma unroll
            for (int k = 0; k < 4; ++k) acc[i][j][k] = 0.f;

    // buffers: per buf {AH, AL, BH, BL} x 16 KB ; buf1 at +65536
    tile_ld(sb + 0,     Ghi, NN, tid);
    tile_ld(sb + 16384, Glo, NN, tid);
    tile_ld(sb + 32768, Ehi, NN, tid);
    tile_ld(sb + 49152, Elo, NN, tid);
    asm volatile("cp.async.commit_group;" ::: "memory");

    const int li8 = lane & 7, sel = lane >> 3;
    int buf = 0;
    for (int c = 0; c < 36; ++c) {
        if (c + 1 < 36) {
            const uint32_t nb = sb + (buf ^ 1) * 65536;
            tile_ld(nb + 0,     Ghi + (size_t)(c + 1) * 64, NN, tid);
            tile_ld(nb + 16384, Glo + (size_t)(c + 1) * 64, NN, tid);
            tile_ld(nb + 32768, Ehi + (size_t)(c + 1) * 64, NN, tid);
            tile_ld(nb + 49152, Elo + (size_t)(c + 1) * 64, NN, tid);
            asm volatile("cp.async.commit_group;" ::: "memory");
            asm volatile("cp.async.wait_group 1;" ::: "memory");
        } else {
            asm volatile("cp.async.wait_group 0;" ::: "memory");
        }
        __syncthreads();
        const uint32_t cb = sb + buf * 65536;
#pragma unroll
        for (int ks = 0; ks < 4; ++ks) {
            const int kb = ks * 32;
            uint32_t ah[4][4], al[4][4], bh[2][4], bl[2][4];
#pragma unroll
            for (int mi = 0; mi < 4; ++mi) {
                int row = mW + mi * 16 + li8 + (sel & 1) * 8;
                uint32_t o = (uint32_t)(row * 128 + kb + (sel >> 1) * 16);
                o ^= (o >> 3) & 0x70;
                LDSM4(ah[mi], cb + o);
                LDSM4(al[mi], cb + 16384 + o);
            }
#pragma unroll
            for (int nq = 0; nq < 2; ++nq) {
                int row = nW + nq * 16 + li8 + (sel >> 1) * 8;
                uint32_t o = (uint32_t)(row * 128 + kb + (sel & 1) * 16);
                o ^= (o >> 3) & 0x70;
                LDSM4(bh[nq], cb + 32768 + o);
                LDSM4(bl[nq], cb + 49152 + o);
            }
#pragma unroll
            for (int mi = 0; mi < 4; ++mi)
#pragma unroll
                for (int ni = 0; ni < 4; ++ni) {
                    const int q = ni >> 1, p = (ni & 1) * 2;
                    MMA(acc[mi][ni], ah[mi], bh[q][p], bh[q][p + 1]);
                    MMA(acc[mi][ni], ah[mi], bl[q][p], bl[q][p + 1]);
                    MMA(acc[mi][ni], al[mi], bh[q][p], bh[q][p + 1]);
                }
        }
        __syncthreads();
        buf ^= 1;
    }

    // epilogue: stage[j_local][m], then packed split write (hi,hi,lo)
    float (*stage)[129] = (float(*)[129])smem;
    const int g8 = lane >> 2, tg = lane & 3;
#pragma unroll
    for (int mi = 0; mi < 4; ++mi) {
        const int r0 = mW + mi * 16 + g8;
#pragma unroll
        for (int ni = 0; ni < 4; ++ni) {
            const int c = nW + ni * 8 + tg * 2;
            stage[c][r0]         = acc[mi][ni][0];
            stage[c + 1][r0]     = acc[mi][ni][1];
            stage[c][r0 + 8]     = acc[mi][ni][2];
            stage[c + 1][r0 + 8] = acc[mi][ni][3];
        }
    }
    __syncthreads();
    for (int e = tid; e < 16384; e += 256) {
        int jl = e >> 7, m = e & 127;
        float v = stage[jl][m];
        bf16 h = __float2bfloat16(v);
        bf16 l = __float2bfloat16(v - __bfloat162float(h));
        size_t o = (size_t)(j0 + jl) * K3F;
        OmT[o + m]       = h;
        OmT[o + 128 + m] = h;
        OmT[o + 256 + m] = l;
    }
}

// ---------------------------------------------------------------------------
// x split-transpose: X fp32 [C,N] per batch -> XT bf16 [N, K3C] (hi,hi,lo)
// ---------------------------------------------------------------------------
__global__ void __launch_bounds__(256)
xsplitT(const float* __restrict__ X, bf16* __restrict__ XT)
{
    extern __shared__ char smem[];
    float (*stage)[129] = (float(*)[129])smem;
    const int b = blockIdx.z;
    const int c0 = blockIdx.y * 128, n0 = blockIdx.x * 128;
    X  += (size_t)b * CC * NN;
    XT += (size_t)b * NN * K3C;
    const int tid = threadIdx.x;

    for (int e = tid; e < 16384; e += 256) {
        int cc = e >> 7, nn = e & 127;
        stage[nn][cc] = X[(size_t)(c0 + cc) * NN + n0 + nn];
    }
    __syncthreads();
    for (int e = tid; e < 16384; e += 256) {
        int nn = e >> 7, cc = e & 127;
        float v = stage[nn][cc];
        bf16 h = __float2bfloat16(v);
        bf16 l = __float2bfloat16(v - __bfloat162float(h));
        size_t o = (size_t)(n0 + nn) * K3C;
        XT[o + c0 + cc]        = h;
        XT[o + 512 + c0 + cc]  = h;
        XT[o + 1024 + c0 + cc] = l;
    }
}

// weight split: W fp32 [M,K] -> O bf16 [M, 3K] (hi,lo,hi)
__global__ void __launch_bounds__(256)
wsplit(const float* __restrict__ W, bf16* __restrict__ O, int K)
{
    const int idx = blockIdx.x * 256 + threadIdx.x;
    const int m = idx / K, k = idx % K;
    float v = W[idx];
    bf16 h = __float2bfloat16(v);
    bf16 l = __float2bfloat16(v - __bfloat162float(h));
    const size_t o = (size_t)m * 3 * K;
    O[o + k]         = h;
    O[o + K + k]     = l;
    O[o + 2 * K + k] = h;
}

// ---------------------------------------------------------------------------

extern "C" void kernel_launch(void* const* d_in, const int* in_sizes, int n_in,
                              void* d_out, int out_size)
{
    const float* x    = (const float*)d_in[0];
    const float* x_h  = (const float*)d_in[1];
    const float* x_v  = (const float*)d_in[2];
    const float* Wa   = (const float*)d_in[3];
    const float* ba   = (const float*)d_in[4];
    const float* ga   = (const float*)d_in[5];
    const float* ta   = (const float*)d_in[6];
    const float* Wv   = (const float*)d_in[7];
    const float* bv   = (const float*)d_in[8];
    const float* gv   = (const float*)d_in[9];
    const float* tv   = (const float*)d_in[10];
    const float* Wgav = (const float*)d_in[11];
    const float* bgav = (const float*)d_in[12];
    const float* Wgah = (const float*)d_in[13];
    const float* bgah = (const float*)d_in[14];
    const float* Wfav = (const float*)d_in[15];
    const float* bfav = (const float*)d_in[16];
    const float* Wfah = (const float*)d_in[17];
    const float* bfah = (const float*)d_in[18];
    float* out = (float*)d_out;

    float *ps, *inv, *gav, *gah;
    bf16 *Ehi, *Elo, *xT, *xvT, *xhT, *faT, *fvT, *fhT;
    bf16 *Wap, *Wvp, *Wgavp, *Wgahp, *Wfavp, *Wfahp;
    bf16 *ghi, *glo, *OmT;
    cudaGetSymbolAddress((void**)&Ehi,   d_Ehi);
    cudaGetSymbolAddress((void**)&Elo,   d_Elo);
    cudaGetSymbolAddress((void**)&ps,    d_ps);
    cudaGetSymbolAddress((void**)&inv,   d_inv);
    cudaGetSymbolAddress((void**)&xT,    d_xT);
    cudaGetSymbolAddress((void**)&xvT,   d_xvT);
    cudaGetSymbolAddress((void**)&xhT,   d_xhT);
    cudaGetSymbolAddress((void**)&faT,   d_faT);
    cudaGetSymbolAddress((void**)&fvT,   d_fvT);
    cudaGetSymbolAddress((void**)&fhT,   d_fhT);
    cudaGetSymbolAddress((void**)&Wap,   d_Wap);
    cudaGetSymbolAddress((void**)&Wvp,   d_Wvp);
    cudaGetSymbolAddress((void**)&Wgavp, d_Wgavp);
    cudaGetSymbolAddress((void**)&Wgahp, d_Wgahp);
    cudaGetSymbolAddress((void**)&Wfavp, d_Wfavp);
    cudaGetSymbolAddress((void**)&Wfahp, d_Wfahp);
    cudaGetSymbolAddress((void**)&gav,   d_gav);
    cudaGetSymbolAddress((void**)&gah,   d_gah);
    cudaGetSymbolAddress((void**)&ghi,   d_ghi);
    cudaGetSymbolAddress((void**)&glo,   d_glo);
    cudaGetSymbolAddress((void**)&OmT,   d_OmT);

    const int SMEM_CV = 66560;
    const int SMEM_SC = 65536;
    const int SMEM_AP = 131072;
    const int SMEM_ST = 66048;
    cudaFuncSetAttribute(hmma_conv<0,0>, cudaFuncAttributeMaxDynamicSharedMemorySize, SMEM_CV);
    cudaFuncSetAttribute(hmma_conv<0,1>, cudaFuncAttributeMaxDynamicSharedMemorySize, SMEM_CV);
    cudaFuncSetAttribute(hmma_conv<1,0>, cudaFuncAttributeMaxDynamicSharedMemorySize, SMEM_CV);
    cudaFuncSetAttribute(hmma_conv<2,0>, cudaFuncAttributeMaxDynamicSharedMemorySize, SMEM_CV);
    cudaFuncSetAttribute(hmma_score,     cudaFuncAttributeMaxDynamicSharedMemorySize, SMEM_SC);
    cudaFuncSetAttribute(apply_fused,    cudaFuncAttributeMaxDynamicSharedMemorySize, SMEM_AP);
    cudaFuncSetAttribute(xsplitT,        cudaFuncAttributeMaxDynamicSharedMemorySize, SMEM_ST);

    const size_t sX  = (size_t)CC * NN;
    const size_t sXT = (size_t)NN * K3C;
    const size_t sF  = (size_t)NN * K3F;
    const size_t sG  = (size_t)MD * NN;
    const size_t halfOut = (size_t)BB * CC * NN;
    const float alpha = 0.08838834764831845f;  // 128^-0.5

    dim3 blk(256);
    dim3 gXT   (NN / 128, CC / 128, BB);
    dim3 gConv (NN / 128, 1, BB);
    dim3 gScore(NN / 128, NN / 128, BB);
    dim3 gApply(NN / 128, 1, BB);
    dim3 gOut  (NN / 128, CC / 128, BB);
    dim3 gInv  (NN / 256, 1, BB);
    dim3 gGs   ((MD * NN / 2) / 256, 1, BB);

    // Phase 0: pack inputs + weights
    xsplitT<<<gXT, blk, SMEM_ST>>>(x,   xT);
    xsplitT<<<gXT, blk, SMEM_ST>>>(x_v, xvT);
    xsplitT<<<gXT, blk, SMEM_ST>>>(x_h, xhT);
    wsplit<<<(MD * CC) / 256, blk>>>(Wa,   Wap,   CC);
    wsplit<<<(MD * CC) / 256, blk>>>(Wv,   Wvp,   CC);
    wsplit<<<(MD * CC) / 256, blk>>>(Wgav, Wgavp, CC);
    wsplit<<<(MD * CC) / 256, blk>>>(Wgah, Wgahp, CC);
    wsplit<<<(CC * MD) / 256, blk>>>(Wfav, Wfavp, MD);
    wsplit<<<(CC * MD) / 256, blk>>>(Wfah, Wfahp, MD);

    // Phase 1: input convs (HMMA)
    hmma_conv<0,1><<<gConv, blk, SMEM_CV>>>(Wap,   xT,  sXT, K3C, nullptr, 0, faT, sF, ba,   ga, ta, nullptr, 0);
    hmma_conv<0,0><<<gConv, blk, SMEM_CV>>>(Wvp,   xvT, sXT, K3C, nullptr, 0, fvT, sF, bv,   gv, tv, nullptr, 0);
    hmma_conv<0,0><<<gConv, blk, SMEM_CV>>>(Wvp,   xhT, sXT, K3C, nullptr, 0, fhT, sF, bv,   gv, tv, nullptr, 0);
    hmma_conv<1,0><<<gConv, blk, SMEM_CV>>>(Wgavp, xT,  sXT, K3C, gav, sG, nullptr, 0, bgav, nullptr, nullptr, nullptr, 0);
    hmma_conv<1,0><<<gConv, blk, SMEM_CV>>>(Wgahp, xT,  sXT, K3C, gah, sG, nullptr, 0, bgah, nullptr, nullptr, nullptr, 0);

    // Pass ah -> o_h
    hmma_score<<<gScore, blk, SMEM_SC>>>(faT, fhT, sF, Ehi, Elo, ps, alpha);
    finalize_inv<<<gInv, blk>>>(ps, inv);
    gscale<<<gGs, blk>>>(gah, inv, ghi, glo);
    apply_fused<<<gApply, blk, SMEM_AP>>>(ghi, glo, Ehi, Elo, OmT);
    hmma_conv<2,0><<<gOut, blk, SMEM_CV>>>(Wfahp, OmT, sF, K3F, out, sX, nullptr, 0, bfah, nullptr, nullptr, x, sX);

    // Pass av -> o_v
    hmma_score<<<gScore, blk, SMEM_SC>>>(faT, fvT, sF, Ehi, Elo, ps, alpha);
    finalize_inv<<<gInv, blk>>>(ps, inv);
    gscale<<<gGs, blk>>>(gav, inv, ghi, glo);
    apply_fused<<<gApply, blk, SMEM_AP>>>(ghi, glo, Ehi, Elo, OmT);
    hmma_conv<2,0><<<gOut, blk, SMEM_CV>>>(Wfavp, OmT, sF, K3F, out + halfOut, sX, nullptr, 0, bfav, nullptr, nullptr, x, sX);
}

// round 13
// speedup vs baseline: 1.1390x; 1.1390x over previous
#include <cuda_runtime.h>
#include <cuda_bf16.h>
#include <cstdint>
#include <cstddef>

#define BB 8
#define CC 512
#define NN 2304
#define MD 128
#define K3F 384     // 3*MD  packed K (score operands, out-conv K)
#define K3C 1536    // 3*CC  packed K (input conv K)
#define NTILE 18    // NN / 128

typedef __nv_bfloat16 bf16;

// ---- scratch (per-pass duplicated where needed) ---------------------------
static __device__ bf16  d_Ehi1[(size_t)BB * NN * NN], d_Elo1[(size_t)BB * NN * NN];
static __device__ bf16  d_Ehi2[(size_t)BB * NN * NN], d_Elo2[(size_t)BB * NN * NN];
static __device__ float d_ps1 [(size_t)BB * NTILE * NN], d_ps2[(size_t)BB * NTILE * NN];
static __device__ float d_inv1[BB * NN], d_inv2[BB * NN];
static __device__ bf16  d_xT  [(size_t)BB * NN * K3C];
static __device__ bf16  d_xvT [(size_t)BB * NN * K3C];
static __device__ bf16  d_xhT [(size_t)BB * NN * K3C];
static __device__ bf16  d_faT [(size_t)BB * NN * K3F];
static __device__ bf16  d_fvT [(size_t)BB * NN * K3F];
static __device__ bf16  d_fhT [(size_t)BB * NN * K3F];
static __device__ bf16  d_Wap  [MD * K3C];
static __device__ bf16  d_Wvp  [MD * K3C];
static __device__ bf16  d_Wgavp[MD * K3C];
static __device__ bf16  d_Wgahp[MD * K3C];
static __device__ bf16  d_Wfavp[CC * K3F];
static __device__ bf16  d_Wfahp[CC * K3F];
static __device__ float d_gav [(size_t)BB * MD * NN];
static __device__ float d_gah [(size_t)BB * MD * NN];
static __device__ bf16  d_ghi1[(size_t)BB * MD * NN], d_glo1[(size_t)BB * MD * NN];
static __device__ bf16  d_ghi2[(size_t)BB * MD * NN], d_glo2[(size_t)BB * MD * NN];
static __device__ bf16  d_OmT1[(size_t)BB * NN * K3F];
static __device__ bf16  d_OmT2[(size_t)BB * NN * K3F];

// ---- host-side streams/events (created once at program init) --------------
static cudaStream_t g_s1 = 0;
static cudaEvent_t  g_evFork = 0, g_evXT = 0, g_evFA = 0, g_evFH = 0, g_evEnd = 0;
namespace {
struct HXInit {
    HXInit() {
        cudaStreamCreateWithFlags(&g_s1, cudaStreamNonBlocking);
        cudaEventCreateWithFlags(&g_evFork, cudaEventDisableTiming);
        cudaEventCreateWithFlags(&g_evXT,   cudaEventDisableTiming);
        cudaEventCreateWithFlags(&g_evFA,   cudaEventDisableTiming);
        cudaEventCreateWithFlags(&g_evFH,   cudaEventDisableTiming);
        cudaEventCreateWithFlags(&g_evEnd,  cudaEventDisableTiming);
    }
} g_hx_init;
}

__device__ __forceinline__ uint32_t smem_u32(const void* p) {
    uint32_t a;
    asm("{ .reg .u64 t; cvta.to.shared.u64 t, %1; cvt.u32.u64 %0, t; }" : "=r"(a) : "l"(p));
    return a;
}

// 128-row x 128-byte bf16 tile -> smem with SW128 swizzle
__device__ __forceinline__ void tile_ld(uint32_t sdst, const bf16* __restrict__ g,
                                        int ld, int tid) {
#pragma unroll
    for (int it = 0; it < 4; ++it) {
        int s = tid + it * 256;
        int r = s >> 3, c = s & 7;
        uint32_t o = (uint32_t)(r * 128 + c * 16);
        o ^= (o >> 3) & 0x70;
        asm volatile("cp.async.cg.shared.global [%0], [%1], 16;"
                     :: "r"(sdst + o), "l"(g + (size_t)r * ld + c * 8) : "memory");
    }
}
// 128-row interleaved hi|lo tile (32 k each): row bytes [0,64)=hi, [64,128)=lo
__device__ __forceinline__ void tile_ld32(uint32_t sdst, const bf16* __restrict__ hi,
                                          const bf16* __restrict__ lo, int ld, int tid) {
#pragma unroll
    for (int it = 0; it < 2; ++it) {
        int s = tid + it * 256;
        int r = s >> 2, q = s & 3;
        uint32_t o = (uint32_t)(r * 128 + q * 16);
        uint32_t o1 = o ^ ((o >> 3) & 0x70);
        uint32_t o2 = (o + 64) ^ (((o + 64) >> 3) & 0x70);
        asm volatile("cp.async.cg.shared.global [%0], [%1], 16;"
                     :: "r"(sdst + o1), "l"(hi + (size_t)r * ld + q * 8) : "memory");
        asm volatile("cp.async.cg.shared.global [%0], [%1], 16;"
                     :: "r"(sdst + o2), "l"(lo + (size_t)r * ld + q * 8) : "memory");
    }
}

#define LDSM4(d, a)                                                          \
    asm volatile("ldmatrix.sync.aligned.m8n8.x4.shared.b16 {%0,%1,%2,%3}, [%4];" \
        : "=r"((d)[0]), "=r"((d)[1]), "=r"((d)[2]), "=r"((d)[3]) : "r"(a))
#define MMA(ac, af, b0, b1)                                                  \
    asm volatile("mma.sync.aligned.m16n8k16.row.col.f32.bf16.bf16.f32 "      \
        "{%0,%1,%2,%3}, {%4,%5,%6,%7}, {%8,%9}, {%0,%1,%2,%3};"              \
        : "+f"((ac)[0]), "+f"((ac)[1]), "+f"((ac)[2]), "+f"((ac)[3])         \
        : "r"((af)[0]), "r"((af)[1]), "r"((af)[2]), "r"((af)[3]),            \
          "r"(b0), "r"(b1))

// ---------------------------------------------------------------------------
// Generic conv HMMA. EPI 0: BN-ReLU -> fT packed; EPI 1: +bias fp32;
// EPI 2: +bias + resid fp32.
// ---------------------------------------------------------------------------
template<int EPI, int PAT>
__global__ void __launch_bounds__(256)
hmma_conv(const bf16* __restrict__ Aw, const bf16* __restrict__ Bx, size_t sB,
          int K3, float* __restrict__ Cf, size_t sC,
          bf16* __restrict__ O1, size_t sO,
          const float* __restrict__ bias,
          const float* __restrict__ gam, const float* __restrict__ bet,
          const float* __restrict__ resid, size_t sR)
{
    extern __shared__ char smem[];
    const uint32_t sb = smem_u32(smem);
    const int tid = threadIdx.x, wid = tid >> 5, lane = tid & 31;
    const int b = blockIdx.z;
    const int m0 = blockIdx.y * 128, n0 = blockIdx.x * 128;
    Aw += (size_t)m0 * K3;
    Bx += (size_t)b * sB + (size_t)n0 * K3;
    if (EPI == 0) { O1 += (size_t)b * sO; }
    else          { Cf += (size_t)b * sC; if (EPI == 2) resid += (size_t)b * sR; }

    const int mW = (wid & 1) * 64, nW = (wid >> 1) * 32;
    float acc[4][4][4];
#pragma unroll
    for (int i = 0; i < 4; ++i)
#pragma unroll
        for (int j = 0; j < 4; ++j)
#pragma unroll
            for (int k = 0; k < 4; ++k) acc[i][j][k] = 0.f;

    const uint32_t oA[2] = { sb, sb + 32768 };
    const uint32_t oB[2] = { sb + 16384, sb + 49152 };
    tile_ld(oA[0], Aw, K3, tid);
    tile_ld(oB[0], Bx, K3, tid);
    asm volatile("cp.async.commit_group;" ::: "memory");

    const int li8 = lane & 7, sel = lane >> 3;
    const int nC = K3 >> 6;
    int buf = 0;
    for (int c = 0; c < nC; ++c) {
        if (c + 1 < nC) {
            tile_ld(oA[buf ^ 1], Aw + (size_t)(c + 1) * 64, K3, tid);
            tile_ld(oB[buf ^ 1], Bx + (size_t)(c + 1) * 64, K3, tid);
            asm volatile("cp.async.commit_group;" ::: "memory");
            asm volatile("cp.async.wait_group 1;" ::: "memory");
        } else {
            asm volatile("cp.async.wait_group 0;" ::: "memory");
        }
        __syncthreads();
        const uint32_t ab = oA[buf], bb = oB[buf];
#pragma unroll
        for (int ks = 0; ks < 4; ++ks) {
            const int kb = ks * 32;
            uint32_t af[4][4], bfr[2][4];
#pragma unroll
            for (int mi = 0; mi < 4; ++mi) {
                int row = mW + mi * 16 + li8 + (sel & 1) * 8;
                uint32_t o = (uint32_t)(row * 128 + kb + (sel >> 1) * 16);
                o ^= (o >> 3) & 0x70;
                LDSM4(af[mi], ab + o);
            }
#pragma unroll
            for (int nq = 0; nq < 2; ++nq) {
                int row = nW + nq * 16 + li8 + (sel >> 1) * 8;
                uint32_t o = (uint32_t)(row * 128 + kb + (sel & 1) * 16);
                o ^= (o >> 3) & 0x70;
                LDSM4(bfr[nq], bb + o);
            }
#pragma unroll
            for (int mi = 0; mi < 4; ++mi)
#pragma unroll
                for (int ni = 0; ni < 4; ++ni)
                    MMA(acc[mi][ni], af[mi],
                        bfr[ni >> 1][(ni & 1) * 2], bfr[ni >> 1][(ni & 1) * 2 + 1]);
        }
        __syncthreads();
        buf ^= 1;
    }

    const int g8 = lane >> 2, tg = lane & 3;
    if (EPI == 0) {
        float (*stage)[129] = (float(*)[129])smem;
        const float rs = rsqrtf(1.f + 1e-5f);
#pragma unroll
        for (int mi = 0; mi < 4; ++mi) {
            const int r0 = mW + mi * 16 + g8, r1 = r0 + 8;
            const float s0 = gam[r0] * rs, b0 = fmaf(bias[r0], s0, bet[r0]);
            const float s1 = gam[r1] * rs, b1 = fmaf(bias[r1], s1, bet[r1]);
#pragma unroll
            for (int ni = 0; ni < 4; ++ni) {
                const int c = nW + ni * 8 + tg * 2;
                stage[c][r0]     = fmaxf(fmaf(acc[mi][ni][0], s0, b0), 0.f);
                stage[c + 1][r0] = fmaxf(fmaf(acc[mi][ni][1], s0, b0), 0.f);
                stage[c][r1]     = fmaxf(fmaf(acc[mi][ni][2], s1, b1), 0.f);
                stage[c + 1][r1] = fmaxf(fmaf(acc[mi][ni][3], s1, b1), 0.f);
            }
        }
        __syncthreads();
        for (int e = tid; e < 16384; e += 256) {
            int nn = e >> 7, m = e & 127;
            float v = stage[nn][m];
            bf16 h = __float2bfloat16(v);
            bf16 l = __float2bfloat16(v - __bfloat162float(h));
            size_t o = (size_t)(n0 + nn) * K3F;
            O1[o + m]       = h;
            O1[o + 128 + m] = PAT ? l : h;
            O1[o + 256 + m] = PAT ? h : l;
        }
    } else {
#pragma unroll
        for (int mi = 0; mi < 4; ++mi) {
            const int r0 = m0 + mW + mi * 16 + g8;
            const float bs0 = bias[r0], bs1 = bias[r0 + 8];
#pragma unroll
            for (int ni = 0; ni < 4; ++ni) {
                const int n = n0 + nW + ni * 8 + tg * 2;
                const size_t i0r = (size_t)r0 * NN + n, i1r = (size_t)(r0 + 8) * NN + n;
                float a0 = acc[mi][ni][0] + bs0, a1 = acc[mi][ni][1] + bs0;
                float a2 = acc[mi][ni][2] + bs1, a3 = acc[mi][ni][3] + bs1;
                if (EPI == 2) {
                    float2 rs0 = *(const float2*)&resid[i0r];
                    float2 rs1 = *(const float2*)&resid[i1r];
                    a0 += rs0.x; a1 += rs0.y; a2 += rs1.x; a3 += rs1.y;
                }
                *(float2*)&Cf[i0r] = make_float2(a0, a1);
                *(float2*)&Cf[i1r] = make_float2(a2, a3);
            }
        }
    }
}

// ---------------------------------------------------------------------------
// Score: E[j,n] = exp(alpha * <faT[j,:], fqT[n,:]>); writes Ehi/Elo + PS.
// ---------------------------------------------------------------------------
__global__ void __launch_bounds__(256)
hmma_score(const bf16* __restrict__ A, const bf16* __restrict__ B, size_t sF,
           bf16* __restrict__ Ehi, bf16* __restrict__ Elo,
           float* __restrict__ PS, float alpha)
{
    extern __shared__ char smem[];
    const uint32_t sb = smem_u32(smem);
    const int tid = threadIdx.x, wid = tid >> 5, lane = tid & 31;
    const int b = blockIdx.z;
    const int i0 = blockIdx.y * 128, j0 = blockIdx.x * 128;
    A += (size_t)b * sF + (size_t)i0 * K3F;
    B += (size_t)b * sF + (size_t)j0 * K3F;
    Ehi += (size_t)b * NN * NN;
    Elo += (size_t)b * NN * NN;

    const int mW = (wid & 1) * 64, nW = (wid >> 1) * 32;
    float acc[4][4][4];
#pragma unroll
    for (int i = 0; i < 4; ++i)
#pragma unroll
        for (int j = 0; j < 4; ++j)
#pragma unroll
            for (int k = 0; k < 4; ++k) acc[i][j][k] = 0.f;

    const uint32_t oA[2] = { sb, sb + 32768 };
    const uint32_t oB[2] = { sb + 16384, sb + 49152 };
    tile_ld(oA[0], A, K3F, tid);
    tile_ld(oB[0], B, K3F, tid);
    asm volatile("cp.async.commit_group;" ::: "memory");

    const int li8 = lane & 7, sel = lane >> 3;
    int buf = 0;
    for (int c = 0; c < 6; ++c) {
        if (c + 1 < 6) {
            tile_ld(oA[buf ^ 1], A + (size_t)(c + 1) * 64, K3F, tid);
            tile_ld(oB[buf ^ 1], B + (size_t)(c + 1) * 64, K3F, tid);
            asm volatile("cp.async.commit_group;" ::: "memory");
            asm volatile("cp.async.wait_group 1;" ::: "memory");
        } else {
            asm volatile("cp.async.wait_group 0;" ::: "memory");
        }
        __syncthreads();
        const uint32_t ab = oA[buf], bb = oB[buf];
#pragma unroll
        for (int ks = 0; ks < 4; ++ks) {
            const int kb = ks * 32;
            uint32_t af[4][4], bfr[2][4];
#pragma unroll
            for (int mi = 0; mi < 4; ++mi) {
                int row = mW + mi * 16 + li8 + (sel & 1) * 8;
                uint32_t o = (uint32_t)(row * 128 + kb + (sel >> 1) * 16);
                o ^= (o >> 3) & 0x70;
                LDSM4(af[mi], ab + o);
            }
#pragma unroll
            for (int nq = 0; nq < 2; ++nq) {
                int row = nW + nq * 16 + li8 + (sel >> 1) * 8;
                uint32_t o = (uint32_t)(row * 128 + kb + (sel & 1) * 16);
                o ^= (o >> 3) & 0x70;
                LDSM4(bfr[nq], bb + o);
            }
#pragma unroll
            for (int mi = 0; mi < 4; ++mi)
#pragma unroll
                for (int ni = 0; ni < 4; ++ni)
                    MMA(acc[mi][ni], af[mi],
                        bfr[ni >> 1][(ni & 1) * 2], bfr[ni >> 1][(ni & 1) * 2 + 1]);
        }
        __syncthreads();
        buf ^= 1;
    }

    const int g8 = lane >> 2, tg = lane & 3;
    float ev[4][4][4];
#pragma unroll
    for (int mi = 0; mi < 4; ++mi)
#pragma unroll
        for (int ni = 0; ni < 4; ++ni)
#pragma unroll
            for (int k = 0; k < 4; ++k)
                ev[mi][ni][k] = __expf(acc[mi][ni][k] * alpha);
#pragma unroll
    for (int mi = 0; mi < 4; ++mi)
#pragma unroll
        for (int ni = 0; ni < 4; ++ni) {
            const int r  = i0 + mW + mi * 16 + g8;
            const int cN = j0 + nW + ni * 8 + tg * 2;
            __nv_bfloat162 h01 = __floats2bfloat162_rn(ev[mi][ni][0], ev[mi][ni][1]);
            __nv_bfloat162 h23 = __floats2bfloat162_rn(ev[mi][ni][2], ev[mi][ni][3]);
            float2 f01 = __bfloat1622float2(h01);
            float2 f23 = __bfloat1622float2(h23);
            __nv_bfloat162 l01 = __floats2bfloat162_rn(ev[mi][ni][0] - f01.x,
                                                       ev[mi][ni][1] - f01.y);
            __nv_bfloat162 l23 = __floats2bfloat162_rn(ev[mi][ni][2] - f23.x,
                                                       ev[mi][ni][3] - f23.y);
            *(__nv_bfloat162*)&Ehi[(size_t)r * NN + cN]       = h01;
            *(__nv_bfloat162*)&Elo[(size_t)r * NN + cN]       = l01;
            *(__nv_bfloat162*)&Ehi[(size_t)(r + 8) * NN + cN] = h23;
            *(__nv_bfloat162*)&Elo[(size_t)(r + 8) * NN + cN] = l23;
        }
    float cs[8];
#pragma unroll
    for (int ni = 0; ni < 4; ++ni)
#pragma unroll
        for (int par = 0; par < 2; ++par) {
            float s = 0.f;
#pragma unroll
            for (int mi = 0; mi < 4; ++mi)
                s += ev[mi][ni][par] + ev[mi][ni][2 + par];
            cs[ni * 2 + par] = s;
        }
#pragma unroll
    for (int o = 4; o <= 16; o <<= 1)
#pragma unroll
        for (int e = 0; e < 8; ++e)
            cs[e] += __shfl_xor_sync(0xffffffffu, cs[e], o);
    float* sP = (float*)smem;
    if (g8 == 0) {
#pragma unroll
        for (int ni = 0; ni < 4; ++ni)
#pragma unroll
            for (int par = 0; par < 2; ++par)
                sP[(wid & 1) * 128 + nW + ni * 8 + tg * 2 + par] = cs[ni * 2 + par];
    }
    __syncthreads();
    if (tid < 128)
        PS[((size_t)(b * NTILE + blockIdx.y)) * NN + j0 + tid] = sP[tid] + sP[128 + tid];
}

// inv[b][n] = 1 / sum_t PS[b][t][n]
__global__ void __launch_bounds__(256)
finalize_inv(const float* __restrict__ PS, float* __restrict__ inv)
{
    const int b = blockIdx.z;
    const int n = blockIdx.x * 256 + threadIdx.x;
    float s = 0.f;
#pragma unroll
    for (int t = 0; t < NTILE; ++t)
        s += PS[((size_t)(b * NTILE + t)) * NN + n];
    inv[b * NN + n] = 1.f / s;
}

// ghi/glo = split(g * inv[n])
__global__ void __launch_bounds__(256)
gscale(const float* __restrict__ g, const float* __restrict__ inv,
       bf16* __restrict__ Ghi, bf16* __restrict__ Glo)
{
    const int b = blockIdx.z;
    const size_t i2 = ((size_t)blockIdx.x * 256 + threadIdx.x) * 2;
    const size_t base = (size_t)b * MD * NN;
    const int n = (int)(i2 % NN);
    float2 v = *(const float2*)&g[base + i2];
    float2 iv = *(const float2*)&inv[b * NN + n];
    v.x *= iv.x; v.y *= iv.y;
    __nv_bfloat162 h = __floats2bfloat162_rn(v.x, v.y);
    float2 f = __bfloat1622float2(h);
    __nv_bfloat162 l = __floats2bfloat162_rn(v.x - f.x, v.y - f.y);
    *(__nv_bfloat162*)&Ghi[base + i2] = h;
    *(__nv_bfloat162*)&Glo[base + i2] = l;
}

// ---------------------------------------------------------------------------
// Apply: om[m,j] = sum_n g'[m,n]*E[j,n]; 3-term bf16, chunk=32, 66KB smem
// (2 CTA/SM co-residency when both passes overlap). Emits OmT packed.
// ---------------------------------------------------------------------------
__global__ void __launch_bounds__(256, 2)
apply_fused(const bf16* __restrict__ Ghi, const bf16* __restrict__ Glo,
            const bf16* __restrict__ Ehi, const bf16* __restrict__ Elo,
            bf16* __restrict__ OmT)
{
    extern __shared__ char smem[];
    const uint32_t sb = smem_u32(smem);
    const int tid = threadIdx.x, wid = tid >> 5, lane = tid & 31;
    const int b = blockIdx.z;
    const int j0 = blockIdx.x * 128;
    Ghi += (size_t)b * MD * NN;
    Glo += (size_t)b * MD * NN;
    Ehi += (size_t)b * NN * NN + (size_t)j0 * NN;
    Elo += (size_t)b * NN * NN + (size_t)j0 * NN;
    OmT += (size_t)b * NN * K3F;

    const int mW = (wid & 1) * 64, nW = (wid >> 1) * 32;
    float acc[4][4][4];
#pragma unroll
    for (int i = 0; i < 4; ++i)
#pragma unroll
        for (int j = 0; j < 4; ++j)
#pragma unroll
            for (int k = 0; k < 4; ++k) acc[i][j][k] = 0.f;

    // per buffer: A interleaved 16KB at +0, E interleaved 16KB at +16384
    tile_ld32(sb + 0,     Ghi, Glo, NN, tid);
    tile_ld32(sb + 16384, Ehi, Elo, NN, tid);
    asm volatile("cp.async.commit_group;" ::: "memory");

    const int li8 = lane & 7, sel = lane >> 3;
    int buf = 0;
    for (int c = 0; c < 72; ++c) {
        if (c + 1 < 72) {
            const uint32_t nb = sb + (buf ^ 1) * 32768;
            tile_ld32(nb + 0,     Ghi + (size_t)(c + 1) * 32, Glo + (size_t)(c + 1) * 32, NN, tid);
            tile_ld32(nb + 16384, Ehi + (size_t)(c + 1) * 32, Elo + (size_t)(c + 1) * 32, NN, tid);
            asm volatile("cp.async.commit_group;" ::: "memory");
            asm volatile("cp.async.wait_group 1;" ::: "memory");
        } else {
            asm volatile("cp.async.wait_group 0;" ::: "memory");
        }
        __syncthreads();
        const uint32_t cb = sb + buf * 32768;
#pragma unroll
        for (int ks = 0; ks < 2; ++ks) {
            const int kb = ks * 32;
            uint32_t ah[4][4], al[4][4], bh[2][4], bl[2][4];
#pragma unroll
            for (int mi = 0; mi < 4; ++mi) {
                int row = mW + mi * 16 + li8 + (sel & 1) * 8;
                uint32_t o  = (uint32_t)(row * 128 + kb + (sel >> 1) * 16);
                uint32_t oh = o ^ ((o >> 3) & 0x70);
                uint32_t ol = (o + 64) ^ (((o + 64) >> 3) & 0x70);
                LDSM4(ah[mi], cb + oh);
                LDSM4(al[mi], cb + ol);
            }
#pragma unroll
            for (int nq = 0; nq < 2; ++nq) {
                int row = nW + nq * 16 + li8 + (sel >> 1) * 8;
                uint32_t o  = (uint32_t)(row * 128 + kb + (sel & 1) * 16);
                uint32_t oh = o ^ ((o >> 3) & 0x70);
                uint32_t ol = (o + 64) ^ (((o + 64) >> 3) & 0x70);
                LDSM4(bh[nq], cb + 16384 + oh);
                LDSM4(bl[nq], cb + 16384 + ol);
            }
#pragma unroll
            for (int mi = 0; mi < 4; ++mi)
#pragma unroll
                for (int ni = 0; ni < 4; ++ni) {
                    const int q = ni >> 1, p = (ni & 1) * 2;
                    MMA(acc[mi][ni], ah[mi], bh[q][p], bh[q][p + 1]);
                    MMA(acc[mi][ni], ah[mi], bl[q][p], bl[q][p + 1]);
                    MMA(acc[mi][ni], al[mi], bh[q][p], bh[q][p + 1]);
                }
        }
        __syncthreads();
        buf ^= 1;
    }

    // epilogue: stage[j_local][m] then packed split write (hi,hi,lo)
    float (*stage)[129] = (float(*)[129])smem;
    const int g8 = lane >> 2, tg = lane & 3;
#pragma unroll
    for (int mi = 0; mi < 4; ++mi) {
        const int r0 = mW + mi * 16 + g8;
#pragma unroll
        for (int ni = 0; ni < 4; ++ni) {
            const int c = nW + ni * 8 + tg * 2;
            stage[c][r0]         = acc[mi][ni][0];
            stage[c + 1][r0]     = acc[mi][ni][1];
            stage[c][r0 + 8]     = acc[mi][ni][2];
            stage[c + 1][r0 + 8] = acc[mi][ni][3];
        }
    }
    __syncthreads();
    for (int e = tid; e < 16384; e += 256) {
        int jl = e >> 7, m = e & 127;
        float v = stage[jl][m];
        bf16 h = __float2bfloat16(v);
        bf16 l = __float2bfloat16(v - __bfloat162float(h));
        size_t o = (size_t)(j0 + jl) * K3F;
        OmT[o + m]       = h;
        OmT[o + 128 + m] = h;
        OmT[o + 256 + m] = l;
    }
}

// ---------------------------------------------------------------------------
__global__ void __launch_bounds__(256)
xsplitT(const float* __restrict__ X, bf16* __restrict__ XT)
{
    extern __shared__ char smem[];
    float (*stage)[129] = (float(*)[129])smem;
    const int b = blockIdx.z;
    const int c0 = blockIdx.y * 128, n0 = blockIdx.x * 128;
    X  += (size_t)b * CC * NN;
    XT += (size_t)b * NN * K3C;
    const int tid = threadIdx.x;

    for (int e = tid; e < 16384; e += 256) {
        int cc = e >> 7, nn = e & 127;
        stage[nn][cc] = X[(size_t)(c0 + cc) * NN + n0 + nn];
    }
    __syncthreads();
    for (int e = tid; e < 16384; e += 256) {
        int nn = e >> 7, cc = e & 127;
        float v = stage[nn][cc];
        bf16 h = __float2bfloat16(v);
        bf16 l = __float2bfloat16(v - __bfloat162float(h));
        size_t o = (size_t)(n0 + nn) * K3C;
        XT[o + c0 + cc]        = h;
        XT[o + 512 + c0 + cc]  = h;
        XT[o + 1024 + c0 + cc] = l;
    }
}

__global__ void __launch_bounds__(256)
wsplit(const float* __restrict__ W, bf16* __restrict__ O, int K)
{
    const int idx = blockIdx.x * 256 + threadIdx.x;
    const int m = idx / K, k = idx % K;
    float v = W[idx];
    bf16 h = __float2bfloat16(v);
    bf16 l = __float2bfloat16(v - __bfloat162float(h));
    const size_t o = (size_t)m * 3 * K;
    O[o + k]         = h;
    O[o + K + k]     = l;
    O[o + 2 * K + k] = h;
}

// ---------------------------------------------------------------------------

extern "C" void kernel_launch(void* const* d_in, const int* in_sizes, int n_in,
                              void* d_out, int out_size)
{
    const float* x    = (const float*)d_in[0];
    const float* x_h  = (const float*)d_in[1];
    const float* x_v  = (const float*)d_in[2];
    const float* Wa   = (const float*)d_in[3];
    const float* ba   = (const float*)d_in[4];
    const float* ga   = (const float*)d_in[5];
    const float* ta   = (const float*)d_in[6];
    const float* Wv   = (const float*)d_in[7];
    const float* bv   = (const float*)d_in[8];
    const float* gv   = (const float*)d_in[9];
    const float* tv   = (const float*)d_in[10];
    const float* Wgav = (const float*)d_in[11];
    const float* bgav = (const float*)d_in[12];
    const float* Wgah = (const float*)d_in[13];
    const float* bgah = (const float*)d_in[14];
    const float* Wfav = (const float*)d_in[15];
    const float* bfav = (const float*)d_in[16];
    const float* Wfah = (const float*)d_in[17];
    const float* bfah = (const float*)d_in[18];
    float* out = (float*)d_out;

    float *ps1, *ps2, *inv1, *inv2, *gav, *gah;
    bf16 *Ehi1, *Elo1, *Ehi2, *Elo2, *xT, *xvT, *xhT, *faT, *fvT, *fhT;
    bf16 *Wap, *Wvp, *Wgavp, *Wgahp, *Wfavp, *Wfahp;
    bf16 *ghi1, *glo1, *ghi2, *glo2, *OmT1, *OmT2;
    cudaGetSymbolAddress((void**)&Ehi1,  d_Ehi1);
    cudaGetSymbolAddress((void**)&Elo1,  d_Elo1);
    cudaGetSymbolAddress((void**)&Ehi2,  d_Ehi2);
    cudaGetSymbolAddress((void**)&Elo2,  d_Elo2);
    cudaGetSymbolAddress((void**)&ps1,   d_ps1);
    cudaGetSymbolAddress((void**)&ps2,   d_ps2);
    cudaGetSymbolAddress((void**)&inv1,  d_inv1);
    cudaGetSymbolAddress((void**)&inv2,  d_inv2);
    cudaGetSymbolAddress((void**)&xT,    d_xT);
    cudaGetSymbolAddress((void**)&xvT,   d_xvT);
    cudaGetSymbolAddress((void**)&xhT,   d_xhT);
    cudaGetSymbolAddress((void**)&faT,   d_faT);
    cudaGetSymbolAddress((void**)&fvT,   d_fvT);
    cudaGetSymbolAddress((void**)&fhT,   d_fhT);
    cudaGetSymbolAddress((void**)&Wap,   d_Wap);
    cudaGetSymbolAddress((void**)&Wvp,   d_Wvp);
    cudaGetSymbolAddress((void**)&Wgavp, d_Wgavp);
    cudaGetSymbolAddress((void**)&Wgahp, d_Wgahp);
    cudaGetSymbolAddress((void**)&Wfavp, d_Wfavp);
    cudaGetSymbolAddress((void**)&Wfahp, d_Wfahp);
    cudaGetSymbolAddress((void**)&gav,   d_gav);
    cudaGetSymbolAddress((void**)&gah,   d_gah);
    cudaGetSymbolAddress((void**)&ghi1,  d_ghi1);
    cudaGetSymbolAddress((void**)&glo1,  d_glo1);
    cudaGetSymbolAddress((void**)&ghi2,  d_ghi2);
    cudaGetSymbolAddress((void**)&glo2,  d_glo2);
    cudaGetSymbolAddress((void**)&OmT1,  d_OmT1);
    cudaGetSymbolAddress((void**)&OmT2,  d_OmT2);

    const int SMEM_CV = 66560;
    const int SMEM_SC = 65536;
    const int SMEM_AP = 66048;
    const int SMEM_ST = 66048;
    cudaFuncSetAttribute(hmma_conv<0,0>, cudaFuncAttributeMaxDynamicSharedMemorySize, SMEM_CV);
    cudaFuncSetAttribute(hmma_conv<0,1>, cudaFuncAttributeMaxDynamicSharedMemorySize, SMEM_CV);
    cudaFuncSetAttribute(hmma_conv<1,0>, cudaFuncAttributeMaxDynamicSharedMemorySize, SMEM_CV);
    cudaFuncSetAttribute(hmma_conv<2,0>, cudaFuncAttributeMaxDynamicSharedMemorySize, SMEM_CV);
    cudaFuncSetAttribute(hmma_score,     cudaFuncAttributeMaxDynamicSharedMemorySize, SMEM_SC);
    cudaFuncSetAttribute(apply_fused,    cudaFuncAttributeMaxDynamicSharedMemorySize, SMEM_AP);
    cudaFuncSetAttribute(xsplitT,        cudaFuncAttributeMaxDynamicSharedMemorySize, SMEM_ST);

    const size_t sXT = (size_t)NN * K3C;
    const size_t sF  = (size_t)NN * K3F;
    const size_t sG  = (size_t)MD * NN;
    const size_t sX  = (size_t)CC * NN;
    const size_t halfOut = (size_t)BB * CC * NN;
    const float alpha = 0.08838834764831845f;  // 128^-0.5

    dim3 blk(256);
    dim3 gXT   (NN / 128, CC / 128, BB);
    dim3 gConv (NN / 128, 1, BB);
    dim3 gScore(NN / 128, NN / 128, BB);
    dim3 gApply(NN / 128, 1, BB);
    dim3 gOut  (NN / 128, CC / 128, BB);
    dim3 gInv  (NN / 256, 1, BB);
    dim3 gGs   ((MD * NN / 2) / 256, 1, BB);

    cudaStream_t s0 = 0, s1 = g_s1;

    // fork
    cudaEventRecord(g_evFork, s0);
    cudaStreamWaitEvent(s1, g_evFork, 0);

    // --- stream 0: x pack + ah-side ---
    xsplitT<<<gXT, blk, SMEM_ST, s0>>>(x, xT);
    cudaEventRecord(g_evXT, s0);
    wsplit<<<(MD * CC) / 256, blk, 0, s0>>>(Wa,   Wap,   CC);
    wsplit<<<(MD * CC) / 256, blk, 0, s0>>>(Wgah, Wgahp, CC);
    wsplit<<<(CC * MD) / 256, blk, 0, s0>>>(Wfah, Wfahp, MD);
    hmma_conv<0,1><<<gConv, blk, SMEM_CV, s0>>>(Wap, xT, sXT, K3C, nullptr, 0, faT, sF, ba, ga, ta, nullptr, 0);
    cudaEventRecord(g_evFA, s0);
    hmma_conv<1,0><<<gConv, blk, SMEM_CV, s0>>>(Wgahp, xT, sXT, K3C, gah, sG, nullptr, 0, bgah, nullptr, nullptr, nullptr, 0);

    // --- stream 1: xv/xh pack + av-side convs ---
    xsplitT<<<gXT, blk, SMEM_ST, s1>>>(x_v, xvT);
    xsplitT<<<gXT, blk, SMEM_ST, s1>>>(x_h, xhT);
    wsplit<<<(MD * CC) / 256, blk, 0, s1>>>(Wv,   Wvp,   CC);
    wsplit<<<(MD * CC) / 256, blk, 0, s1>>>(Wgav, Wgavp, CC);
    wsplit<<<(CC * MD) / 256, blk, 0, s1>>>(Wfav, Wfavp, MD);
    hmma_conv<0,0><<<gConv, blk, SMEM_CV, s1>>>(Wvp, xvT, sXT, K3C, nullptr, 0, fvT, sF, bv, gv, tv, nullptr, 0);
    hmma_conv<0,0><<<gConv, blk, SMEM_CV, s1>>>(Wvp, xhT, sXT, K3C, nullptr, 0, fhT, sF, bv, gv, tv, nullptr, 0);
    cudaEventRecord(g_evFH, s1);
    cudaStreamWaitEvent(s1, g_evXT, 0);
    hmma_conv<1,0><<<gConv, blk, SMEM_CV, s1>>>(Wgavp, xT, sXT, K3C, gav, sG, nullptr, 0, bgav, nullptr, nullptr, nullptr, 0);

    // --- stream 0: pass ah (needs fhT from s1) ---
    cudaStreamWaitEvent(s0, g_evFH, 0);
    hmma_score<<<gScore, blk, SMEM_SC, s0>>>(faT, fhT, sF, Ehi1, Elo1, ps1, alpha);
    finalize_inv<<<gInv, blk, 0, s0>>>(ps1, inv1);
    gscale<<<gGs, blk, 0, s0>>>(gah, inv1, ghi1, glo1);
    apply_fused<<<gApply, blk, SMEM_AP, s0>>>(ghi1, glo1, Ehi1, Elo1, OmT1);
    hmma_conv<2,0><<<gOut, blk, SMEM_CV, s0>>>(Wfahp, OmT1, sF, K3F, out, sX, nullptr, 0, bfah, nullptr, nullptr, x, sX);

    // --- stream 1: pass av (needs faT from s0) ---
    cudaStreamWaitEvent(s1, g_evFA, 0);
    hmma_score<<<gScore, blk, SMEM_SC, s1>>>(faT, fvT, sF, Ehi2, Elo2, ps2, alpha);
    finalize_inv<<<gInv, blk, 0, s1>>>(ps2, inv2);
    gscale<<<gGs, blk, 0, s1>>>(gav, inv2, ghi2, glo2);
    apply_fused<<<gApply, blk, SMEM_AP, s1>>>(ghi2, glo2, Ehi2, Elo2, OmT2);
    hmma_conv<2,0><<<gOut, blk, SMEM_CV, s1>>>(Wfavp, OmT2, sF, K3F, out + halfOut, sX, nullptr, 0, bfav, nullptr, nullptr, x, sX);

    // join
    cudaEventRecord(g_evEnd, s1);
    cudaStreamWaitEvent(s0, g_evEnd, 0);
}

// round 14
// speedup vs baseline: 1.2018x; 1.0551x over previous
#include <cuda_runtime.h>
#include <cuda_bf16.h>
#include <cstdint>
#include <cstddef>

#define BB 8
#define CC 512
#define NN 2304
#define MD 128
#define K3F 384     // 3*MD  packed K (score operands, out-conv K)
#define K3C 1536    // 3*CC  packed K (input conv K)
#define NTILE 18    // NN / 128

typedef __nv_bfloat16 bf16;

// ---- scratch (per-pass duplicated where needed) ---------------------------
static __device__ bf16  d_Ehi1[(size_t)BB * NN * NN], d_Elo1[(size_t)BB * NN * NN];
static __device__ bf16  d_Ehi2[(size_t)BB * NN * NN], d_Elo2[(size_t)BB * NN * NN];
static __device__ float d_ps1 [(size_t)BB * NTILE * NN], d_ps2[(size_t)BB * NTILE * NN];
static __device__ float d_inv1[BB * NN], d_inv2[BB * NN];
static __device__ bf16  d_xT  [(size_t)BB * NN * K3C];
static __device__ bf16  d_xvT [(size_t)BB * NN * K3C];
static __device__ bf16  d_xhT [(size_t)BB * NN * K3C];
static __device__ bf16  d_faT [(size_t)BB * NN * K3F];
static __device__ bf16  d_fvT [(size_t)BB * NN * K3F];
static __device__ bf16  d_fhT [(size_t)BB * NN * K3F];
static __device__ bf16  d_Wap  [MD * K3C];
static __device__ bf16  d_Wvp  [MD * K3C];
static __device__ bf16  d_Wgavp[MD * K3C];
static __device__ bf16  d_Wgahp[MD * K3C];
static __device__ bf16  d_Wfavp[CC * K3F];
static __device__ bf16  d_Wfahp[CC * K3F];
static __device__ float d_gav [(size_t)BB * MD * NN];
static __device__ float d_gah [(size_t)BB * MD * NN];
static __device__ bf16  d_ghi1[(size_t)BB * MD * NN], d_glo1[(size_t)BB * MD * NN];
static __device__ bf16  d_ghi2[(size_t)BB * MD * NN], d_glo2[(size_t)BB * MD * NN];
static __device__ bf16  d_OmT1[(size_t)BB * NN * K3F];
static __device__ bf16  d_OmT2[(size_t)BB * NN * K3F];

// ---- host-side streams/events (created once at program init) --------------
static cudaStream_t g_s1 = 0;
static cudaEvent_t  g_evFork = 0, g_evGAV = 0, g_evFA = 0, g_evFH = 0, g_evEnd = 0;
namespace {
struct HXInit {
    HXInit() {
        cudaStreamCreateWithFlags(&g_s1, cudaStreamNonBlocking);
        cudaEventCreateWithFlags(&g_evFork, cudaEventDisableTiming);
        cudaEventCreateWithFlags(&g_evGAV,  cudaEventDisableTiming);
        cudaEventCreateWithFlags(&g_evFA,   cudaEventDisableTiming);
        cudaEventCreateWithFlags(&g_evFH,   cudaEventDisableTiming);
        cudaEventCreateWithFlags(&g_evEnd,  cudaEventDisableTiming);
    }
} g_hx_init;
}

__device__ __forceinline__ uint32_t smem_u32(const void* p) {
    uint32_t a;
    asm("{ .reg .u64 t; cvta.to.shared.u64 t, %1; cvt.u32.u64 %0, t; }" : "=r"(a) : "l"(p));
    return a;
}

// 128-row x 128-byte bf16 tile -> smem with SW128 swizzle
__device__ __forceinline__ void tile_ld(uint32_t sdst, const bf16* __restrict__ g,
                                        int ld, int tid) {
#pragma unroll
    for (int it = 0; it < 4; ++it) {
        int s = tid + it * 256;
        int r = s >> 3, c = s & 7;
        uint32_t o = (uint32_t)(r * 128 + c * 16);
        o ^= (o >> 3) & 0x70;
        asm volatile("cp.async.cg.shared.global [%0], [%1], 16;"
                     :: "r"(sdst + o), "l"(g + (size_t)r * ld + c * 8) : "memory");
    }
}
// 128-row interleaved hi|lo tile (32 k each): row bytes [0,64)=hi, [64,128)=lo
__device__ __forceinline__ void tile_ld32(uint32_t sdst, const bf16* __restrict__ hi,
                                          const bf16* __restrict__ lo, int ld, int tid) {
#pragma unroll
    for (int it = 0; it < 2; ++it) {
        int s = tid + it * 256;
        int r = s >> 2, q = s & 3;
        uint32_t o = (uint32_t)(r * 128 + q * 16);
        uint32_t o1 = o ^ ((o >> 3) & 0x70);
        uint32_t o2 = (o + 64) ^ (((o + 64) >> 3) & 0x70);
        asm volatile("cp.async.cg.shared.global [%0], [%1], 16;"
                     :: "r"(sdst + o1), "l"(hi + (size_t)r * ld + q * 8) : "memory");
        asm volatile("cp.async.cg.shared.global [%0], [%1], 16;"
                     :: "r"(sdst + o2), "l"(lo + (size_t)r * ld + q * 8) : "memory");
    }
}

#define LDSM4(d, a)                                                          \
    asm volatile("ldmatrix.sync.aligned.m8n8.x4.shared.b16 {%0,%1,%2,%3}, [%4];" \
        : "=r"((d)[0]), "=r"((d)[1]), "=r"((d)[2]), "=r"((d)[3]) : "r"(a))
#define MMA(ac, af, b0, b1)                                                  \
    asm volatile("mma.sync.aligned.m16n8k16.row.col.f32.bf16.bf16.f32 "      \
        "{%0,%1,%2,%3}, {%4,%5,%6,%7}, {%8,%9}, {%0,%1,%2,%3};"              \
        : "+f"((ac)[0]), "+f"((ac)[1]), "+f"((ac)[2]), "+f"((ac)[3])         \
        : "r"((af)[0]), "r"((af)[1]), "r"((af)[2]), "r"((af)[3]),            \
          "r"(b0), "r"(b1))

// ---------------------------------------------------------------------------
// Generic conv HMMA. EPI 0: BN-ReLU -> fT packed; EPI 1: +bias fp32;
// EPI 2: +bias + resid fp32.  (256,2): allow cross-stream SM pairing.
// ---------------------------------------------------------------------------
template<int EPI, int PAT>
__global__ void __launch_bounds__(256, 2)
hmma_conv(const bf16* __restrict__ Aw, const bf16* __restrict__ Bx, size_t sB,
          int K3, float* __restrict__ Cf, size_t sC,
          bf16* __restrict__ O1, size_t sO,
          const float* __restrict__ bias,
          const float* __restrict__ gam, const float* __restrict__ bet,
          const float* __restrict__ resid, size_t sR)
{
    extern __shared__ char smem[];
    const uint32_t sb = smem_u32(smem);
    const int tid = threadIdx.x, wid = tid >> 5, lane = tid & 31;
    const int b = blockIdx.z;
    const int m0 = blockIdx.y * 128, n0 = blockIdx.x * 128;
    Aw += (size_t)m0 * K3;
    Bx += (size_t)b * sB + (size_t)n0 * K3;
    if (EPI == 0) { O1 += (size_t)b * sO; }
    else          { Cf += (size_t)b * sC; if (EPI == 2) resid += (size_t)b * sR; }

    const int mW = (wid & 1) * 64, nW = (wid >> 1) * 32;
    float acc[4][4][4];
#pragma unroll
    for (int i = 0; i < 4; ++i)
#pragma unroll
        for (int j = 0; j < 4; ++j)
#pragma unroll
            for (int k = 0; k < 4; ++k) acc[i][j][k] = 0.f;

    const uint32_t oA[2] = { sb, sb + 32768 };
    const uint32_t oB[2] = { sb + 16384, sb + 49152 };
    tile_ld(oA[0], Aw, K3, tid);
    tile_ld(oB[0], Bx, K3, tid);
    asm volatile("cp.async.commit_group;" ::: "memory");

    const int li8 = lane & 7, sel = lane >> 3;
    const int nC = K3 >> 6;
    int buf = 0;
    for (int c = 0; c < nC; ++c) {
        if (c + 1 < nC) {
            tile_ld(oA[buf ^ 1], Aw + (size_t)(c + 1) * 64, K3, tid);
            tile_ld(oB[buf ^ 1], Bx + (size_t)(c + 1) * 64, K3, tid);
            asm volatile("cp.async.commit_group;" ::: "memory");
            asm volatile("cp.async.wait_group 1;" ::: "memory");
        } else {
            asm volatile("cp.async.wait_group 0;" ::: "memory");
        }
        __syncthreads();
        const uint32_t ab = oA[buf], bb = oB[buf];
#pragma unroll
        for (int ks = 0; ks < 4; ++ks) {
            const int kb = ks * 32;
            uint32_t af[4][4], bfr[2][4];
#pragma unroll
            for (int mi = 0; mi < 4; ++mi) {
                int row = mW + mi * 16 + li8 + (sel & 1) * 8;
                uint32_t o = (uint32_t)(row * 128 + kb + (sel >> 1) * 16);
                o ^= (o >> 3) & 0x70;
                LDSM4(af[mi], ab + o);
            }
#pragma unroll
            for (int nq = 0; nq < 2; ++nq) {
                int row = nW + nq * 16 + li8 + (sel >> 1) * 8;
                uint32_t o = (uint32_t)(row * 128 + kb + (sel & 1) * 16);
                o ^= (o >> 3) & 0x70;
                LDSM4(bfr[nq], bb + o);
            }
#pragma unroll
            for (int mi = 0; mi < 4; ++mi)
#pragma unroll
                for (int ni = 0; ni < 4; ++ni)
                    MMA(acc[mi][ni], af[mi],
                        bfr[ni >> 1][(ni & 1) * 2], bfr[ni >> 1][(ni & 1) * 2 + 1]);
        }
        __syncthreads();
        buf ^= 1;
    }

    const int g8 = lane >> 2, tg = lane & 3;
    if (EPI == 0) {
        float (*stage)[129] = (float(*)[129])smem;
        const float rs = rsqrtf(1.f + 1e-5f);
#pragma unroll
        for (int mi = 0; mi < 4; ++mi) {
            const int r0 = mW + mi * 16 + g8, r1 = r0 + 8;
            const float s0 = gam[r0] * rs, b0 = fmaf(bias[r0], s0, bet[r0]);
            const float s1 = gam[r1] * rs, b1 = fmaf(bias[r1], s1, bet[r1]);
#pragma unroll
            for (int ni = 0; ni < 4; ++ni) {
                const int c = nW + ni * 8 + tg * 2;
                stage[c][r0]     = fmaxf(fmaf(acc[mi][ni][0], s0, b0), 0.f);
                stage[c + 1][r0] = fmaxf(fmaf(acc[mi][ni][1], s0, b0), 0.f);
                stage[c][r1]     = fmaxf(fmaf(acc[mi][ni][2], s1, b1), 0.f);
                stage[c + 1][r1] = fmaxf(fmaf(acc[mi][ni][3], s1, b1), 0.f);
            }
        }
        __syncthreads();
        for (int e = tid; e < 16384; e += 256) {
            int nn = e >> 7, m = e & 127;
            float v = stage[nn][m];
            bf16 h = __float2bfloat16(v);
            bf16 l = __float2bfloat16(v - __bfloat162float(h));
            size_t o = (size_t)(n0 + nn) * K3F;
            O1[o + m]       = h;
            O1[o + 128 + m] = PAT ? l : h;
            O1[o + 256 + m] = PAT ? h : l;
        }
    } else {
#pragma unroll
        for (int mi = 0; mi < 4; ++mi) {
            const int r0 = m0 + mW + mi * 16 + g8;
            const float bs0 = bias[r0], bs1 = bias[r0 + 8];
#pragma unroll
            for (int ni = 0; ni < 4; ++ni) {
                const int n = n0 + nW + ni * 8 + tg * 2;
                const size_t i0r = (size_t)r0 * NN + n, i1r = (size_t)(r0 + 8) * NN + n;
                float a0 = acc[mi][ni][0] + bs0, a1 = acc[mi][ni][1] + bs0;
                float a2 = acc[mi][ni][2] + bs1, a3 = acc[mi][ni][3] + bs1;
                if (EPI == 2) {
                    float2 rs0 = *(const float2*)&resid[i0r];
                    float2 rs1 = *(const float2*)&resid[i1r];
                    a0 += rs0.x; a1 += rs0.y; a2 += rs1.x; a3 += rs1.y;
                }
                *(float2*)&Cf[i0r] = make_float2(a0, a1);
                *(float2*)&Cf[i1r] = make_float2(a2, a3);
            }
        }
    }
}

// ---------------------------------------------------------------------------
// Score: E[j,n] = exp(alpha * <faT[j,:], fqT[n,:]>); writes Ehi/Elo + PS.
// ---------------------------------------------------------------------------
__global__ void __launch_bounds__(256, 2)
hmma_score(const bf16* __restrict__ A, const bf16* __restrict__ B, size_t sF,
           bf16* __restrict__ Ehi, bf16* __restrict__ Elo,
           float* __restrict__ PS, float alpha)
{
    extern __shared__ char smem[];
    const uint32_t sb = smem_u32(smem);
    const int tid = threadIdx.x, wid = tid >> 5, lane = tid & 31;
    const int b = blockIdx.z;
    const int i0 = blockIdx.y * 128, j0 = blockIdx.x * 128;
    A += (size_t)b * sF + (size_t)i0 * K3F;
    B += (size_t)b * sF + (size_t)j0 * K3F;
    Ehi += (size_t)b * NN * NN;
    Elo += (size_t)b * NN * NN;

    const int mW = (wid & 1) * 64, nW = (wid >> 1) * 32;
    float acc[4][4][4];
#pragma unroll
    for (int i = 0; i < 4; ++i)
#pragma unroll
        for (int j = 0; j < 4; ++j)
#pragma unroll
            for (int k = 0; k < 4; ++k) acc[i][j][k] = 0.f;

    const uint32_t oA[2] = { sb, sb + 32768 };
    const uint32_t oB[2] = { sb + 16384, sb + 49152 };
    tile_ld(oA[0], A, K3F, tid);
    tile_ld(oB[0], B, K3F, tid);
    asm volatile("cp.async.commit_group;" ::: "memory");

    const int li8 = lane & 7, sel = lane >> 3;
    int buf = 0;
    for (int c = 0; c < 6; ++c) {
        if (c + 1 < 6) {
            tile_ld(oA[buf ^ 1], A + (size_t)(c + 1) * 64, K3F, tid);
            tile_ld(oB[buf ^ 1], B + (size_t)(c + 1) * 64, K3F, tid);
            asm volatile("cp.async.commit_group;" ::: "memory");
            asm volatile("cp.async.wait_group 1;" ::: "memory");
        } else {
            asm volatile("cp.async.wait_group 0;" ::: "memory");
        }
        __syncthreads();
        const uint32_t ab = oA[buf], bb = oB[buf];
#pragma unroll
        for (int ks = 0; ks < 4; ++ks) {
            const int kb = ks * 32;
            uint32_t af[4][4], bfr[2][4];
#pragma unroll
            for (int mi = 0; mi < 4; ++mi) {
                int row = mW + mi * 16 + li8 + (sel & 1) * 8;
                uint32_t o = (uint32_t)(row * 128 + kb + (sel >> 1) * 16);
                o ^= (o >> 3) & 0x70;
                LDSM4(af[mi], ab + o);
            }
#pragma unroll
            for (int nq = 0; nq < 2; ++nq) {
                int row = nW + nq * 16 + li8 + (sel >> 1) * 8;
                uint32_t o = (uint32_t)(row * 128 + kb + (sel & 1) * 16);
                o ^= (o >> 3) & 0x70;
                LDSM4(bfr[nq], bb + o);
            }
#pragma unroll
            for (int mi = 0; mi < 4; ++mi)
#pragma unroll
                for (int ni = 0; ni < 4; ++ni)
                    MMA(acc[mi][ni], af[mi],
                        bfr[ni >> 1][(ni & 1) * 2], bfr[ni >> 1][(ni & 1) * 2 + 1]);
        }
        __syncthreads();
        buf ^= 1;
    }

    const int g8 = lane >> 2, tg = lane & 3;
    float ev[4][4][4];
#pragma unroll
    for (int mi = 0; mi < 4; ++mi)
#pragma unroll
        for (int ni = 0; ni < 4; ++ni)
#pragma unroll
            for (int k = 0; k < 4; ++k)
                ev[mi][ni][k] = __expf(acc[mi][ni][k] * alpha);
#pragma unroll
    for (int mi = 0; mi < 4; ++mi)
#pragma unroll
        for (int ni = 0; ni < 4; ++ni) {
            const int r  = i0 + mW + mi * 16 + g8;
            const int cN = j0 + nW + ni * 8 + tg * 2;
            __nv_bfloat162 h01 = __floats2bfloat162_rn(ev[mi][ni][0], ev[mi][ni][1]);
            __nv_bfloat162 h23 = __floats2bfloat162_rn(ev[mi][ni][2], ev[mi][ni][3]);
            float2 f01 = __bfloat1622float2(h01);
            float2 f23 = __bfloat1622float2(h23);
            __nv_bfloat162 l01 = __floats2bfloat162_rn(ev[mi][ni][0] - f01.x,
                                                       ev[mi][ni][1] - f01.y);
            __nv_bfloat162 l23 = __floats2bfloat162_rn(ev[mi][ni][2] - f23.x,
                                                       ev[mi][ni][3] - f23.y);
            *(__nv_bfloat162*)&Ehi[(size_t)r * NN + cN]       = h01;
            *(__nv_bfloat162*)&Elo[(size_t)r * NN + cN]       = l01;
            *(__nv_bfloat162*)&Ehi[(size_t)(r + 8) * NN + cN] = h23;
            *(__nv_bfloat162*)&Elo[(size_t)(r + 8) * NN + cN] = l23;
        }
    float cs[8];
#pragma unroll
    for (int ni = 0; ni < 4; ++ni)
#pragma unroll
        for (int par = 0; par < 2; ++par) {
            float s = 0.f;
#pragma unroll
            for (int mi = 0; mi < 4; ++mi)
                s += ev[mi][ni][par] + ev[mi][ni][2 + par];
            cs[ni * 2 + par] = s;
        }
#pragma unroll
    for (int o = 4; o <= 16; o <<= 1)
#pragma unroll
        for (int e = 0; e < 8; ++e)
            cs[e] += __shfl_xor_sync(0xffffffffu, cs[e], o);
    float* sP = (float*)smem;
    if (g8 == 0) {
#pragma unroll
        for (int ni = 0; ni < 4; ++ni)
#pragma unroll
            for (int par = 0; par < 2; ++par)
                sP[(wid & 1) * 128 + nW + ni * 8 + tg * 2 + par] = cs[ni * 2 + par];
    }
    __syncthreads();
    if (tid < 128)
        PS[((size_t)(b * NTILE + blockIdx.y)) * NN + j0 + tid] = sP[tid] + sP[128 + tid];
}

// inv[b][n] = 1 / sum_t PS[b][t][n]
__global__ void __launch_bounds__(256)
finalize_inv(const float* __restrict__ PS, float* __restrict__ inv)
{
    const int b = blockIdx.z;
    const int n = blockIdx.x * 256 + threadIdx.x;
    float s = 0.f;
#pragma unroll
    for (int t = 0; t < NTILE; ++t)
        s += PS[((size_t)(b * NTILE + t)) * NN + n];
    inv[b * NN + n] = 1.f / s;
}

// ghi/glo = split(g * inv[n])
__global__ void __launch_bounds__(256)
gscale(const float* __restrict__ g, const float* __restrict__ inv,
       bf16* __restrict__ Ghi, bf16* __restrict__ Glo)
{
    const int b = blockIdx.z;
    const size_t i2 = ((size_t)blockIdx.x * 256 + threadIdx.x) * 2;
    const size_t base = (size_t)b * MD * NN;
    const int n = (int)(i2 % NN);
    float2 v = *(const float2*)&g[base + i2];
    float2 iv = *(const float2*)&inv[b * NN + n];
    v.x *= iv.x; v.y *= iv.y;
    __nv_bfloat162 h = __floats2bfloat162_rn(v.x, v.y);
    float2 f = __bfloat1622float2(h);
    __nv_bfloat162 l = __floats2bfloat162_rn(v.x - f.x, v.y - f.y);
    *(__nv_bfloat162*)&Ghi[base + i2] = h;
    *(__nv_bfloat162*)&Glo[base + i2] = l;
}

// ---------------------------------------------------------------------------
// Apply: om[m,j] = sum_n g'[m,n]*E[j,n]; 3-term bf16, chunk=32, 66KB smem,
// 2 CTA/SM. Emits OmT packed [j, K3F] (hi,hi,lo).
// ---------------------------------------------------------------------------
__global__ void __launch_bounds__(256, 2)
apply_fused(const bf16* __restrict__ Ghi, const bf16* __restrict__ Glo,
            const bf16* __restrict__ Ehi, const bf16* __restrict__ Elo,
            bf16* __restrict__ OmT)
{
    extern __shared__ char smem[];
    const uint32_t sb = smem_u32(smem);
    const int tid = threadIdx.x, wid = tid >> 5, lane = tid & 31;
    const int b = blockIdx.z;
    const int j0 = blockIdx.x * 128;
    Ghi += (size_t)b * MD * NN;
    Glo += (size_t)b * MD * NN;
    Ehi += (size_t)b * NN * NN + (size_t)j0 * NN;
    Elo += (size_t)b * NN * NN + (size_t)j0 * NN;
    OmT += (size_t)b * NN * K3F;

    const int mW = (wid & 1) * 64, nW = (wid >> 1) * 32;
    float acc[4][4][4];
#pragma unroll
    for (int i = 0; i < 4; ++i)
#pragma unroll
        for (int j = 0; j < 4; ++j)
#pragma unroll
            for (int k = 0; k < 4; ++k) acc[i][j][k] = 0.f;

    tile_ld32(sb + 0,     Ghi, Glo, NN, tid);
    tile_ld32(sb + 16384, Ehi, Elo, NN, tid);
    asm volatile("cp.async.commit_group;" ::: "memory");

    const int li8 = lane & 7, sel = lane >> 3;
    int buf = 0;
    for (int c = 0; c < 72; ++c) {
        if (c + 1 < 72) {
            const uint32_t nb = sb + (buf ^ 1) * 32768;
            tile_ld32(nb + 0,     Ghi + (size_t)(c + 1) * 32, Glo + (size_t)(c + 1) * 32, NN, tid);
            tile_ld32(nb + 16384, Ehi + (size_t)(c + 1) * 32, Elo + (size_t)(c + 1) * 32, NN, tid);
            asm volatile("cp.async.commit_group;" ::: "memory");
            asm volatile("cp.async.wait_group 1;" ::: "memory");
        } else {
            asm volatile("cp.async.wait_group 0;" ::: "memory");
        }
        __syncthreads();
        const uint32_t cb = sb + buf * 32768;
#pragma unroll
        for (int ks = 0; ks < 2; ++ks) {
            const int kb = ks * 32;
            uint32_t ah[4][4], al[4][4], bh[2][4], bl[2][4];
#pragma unroll
            for (int mi = 0; mi < 4; ++mi) {
                int row = mW + mi * 16 + li8 + (sel & 1) * 8;
                uint32_t o  = (uint32_t)(row * 128 + kb + (sel >> 1) * 16);
                uint32_t oh = o ^ ((o >> 3) & 0x70);
                uint32_t ol = (o + 64) ^ (((o + 64) >> 3) & 0x70);
                LDSM4(ah[mi], cb + oh);
                LDSM4(al[mi], cb + ol);
            }
#pragma unroll
            for (int nq = 0; nq < 2; ++nq) {
                int row = nW + nq * 16 + li8 + (sel >> 1) * 8;
                uint32_t o  = (uint32_t)(row * 128 + kb + (sel & 1) * 16);
                uint32_t oh = o ^ ((o >> 3) & 0x70);
                uint32_t ol = (o + 64) ^ (((o + 64) >> 3) & 0x70);
                LDSM4(bh[nq], cb + 16384 + oh);
                LDSM4(bl[nq], cb + 16384 + ol);
            }
#pragma unroll
            for (int mi = 0; mi < 4; ++mi)
#pragma unroll
                for (int ni = 0; ni < 4; ++ni) {
                    const int q = ni >> 1, p = (ni & 1) * 2;
                    MMA(acc[mi][ni], ah[mi], bh[q][p], bh[q][p + 1]);
                    MMA(acc[mi][ni], ah[mi], bl[q][p], bl[q][p + 1]);
                    MMA(acc[mi][ni], al[mi], bh[q][p], bh[q][p + 1]);
                }
        }
        __syncthreads();
        buf ^= 1;
    }

    float (*stage)[129] = (float(*)[129])smem;
    const int g8 = lane >> 2, tg = lane & 3;
#pragma unroll
    for (int mi = 0; mi < 4; ++mi) {
        const int r0 = mW + mi * 16 + g8;
#pragma unroll
        for (int ni = 0; ni < 4; ++ni) {
            const int c = nW + ni * 8 + tg * 2;
            stage[c][r0]         = acc[mi][ni][0];
            stage[c + 1][r0]     = acc[mi][ni][1];
            stage[c][r0 + 8]     = acc[mi][ni][2];
            stage[c + 1][r0 + 8] = acc[mi][ni][3];
        }
    }
    __syncthreads();
    for (int e = tid; e < 16384; e += 256) {
        int jl = e >> 7, m = e & 127;
        float v = stage[jl][m];
        bf16 h = __float2bfloat16(v);
        bf16 l = __float2bfloat16(v - __bfloat162float(h));
        size_t o = (size_t)(j0 + jl) * K3F;
        OmT[o + m]       = h;
        OmT[o + 128 + m] = h;
        OmT[o + 256 + m] = l;
    }
}

// ---------------------------------------------------------------------------
__global__ void __launch_bounds__(256)
xsplitT(const float* __restrict__ X, bf16* __restrict__ XT)
{
    extern __shared__ char smem[];
    float (*stage)[129] = (float(*)[129])smem;
    const int b = blockIdx.z;
    const int c0 = blockIdx.y * 128, n0 = blockIdx.x * 128;
    X  += (size_t)b * CC * NN;
    XT += (size_t)b * NN * K3C;
    const int tid = threadIdx.x;

    for (int e = tid; e < 16384; e += 256) {
        int cc = e >> 7, nn = e & 127;
        stage[nn][cc] = X[(size_t)(c0 + cc) * NN + n0 + nn];
    }
    __syncthreads();
    for (int e = tid; e < 16384; e += 256) {
        int nn = e >> 7, cc = e & 127;
        float v = stage[nn][cc];
        bf16 h = __float2bfloat16(v);
        bf16 l = __float2bfloat16(v - __bfloat162float(h));
        size_t o = (size_t)(n0 + nn) * K3C;
        XT[o + c0 + cc]        = h;
        XT[o + 512 + c0 + cc]  = h;
        XT[o + 1024 + c0 + cc] = l;
    }
}

__global__ void __launch_bounds__(256)
wsplit(const float* __restrict__ W, bf16* __restrict__ O, int K)
{
    const int idx = blockIdx.x * 256 + threadIdx.x;
    const int m = idx / K, k = idx % K;
    float v = W[idx];
    bf16 h = __float2bfloat16(v);
    bf16 l = __float2bfloat16(v - __bfloat162float(h));
    const size_t o = (size_t)m * 3 * K;
    O[o + k]         = h;
    O[o + K + k]     = l;
    O[o + 2 * K + k] = h;
}

// ---------------------------------------------------------------------------

extern "C" void kernel_launch(void* const* d_in, const int* in_sizes, int n_in,
                              void* d_out, int out_size)
{
    const float* x    = (const float*)d_in[0];
    const float* x_h  = (const float*)d_in[1];
    const float* x_v  = (const float*)d_in[2];
    const float* Wa   = (const float*)d_in[3];
    const float* ba   = (const float*)d_in[4];
    const float* ga   = (const float*)d_in[5];
    const float* ta   = (const float*)d_in[6];
    const float* Wv   = (const float*)d_in[7];
    const float* bv   = (const float*)d_in[8];
    const float* gv   = (const float*)d_in[9];
    const float* tv   = (const float*)d_in[10];
    const float* Wgav = (const float*)d_in[11];
    const float* bgav = (const float*)d_in[12];
    const float* Wgah = (const float*)d_in[13];
    const float* bgah = (const float*)d_in[14];
    const float* Wfav = (const float*)d_in[15];
    const float* bfav = (const float*)d_in[16];
    const float* Wfah = (const float*)d_in[17];
    const float* bfah = (const float*)d_in[18];
    float* out = (float*)d_out;

    float *ps1, *ps2, *inv1, *inv2, *gav, *gah;
    bf16 *Ehi1, *Elo1, *Ehi2, *Elo2, *xT, *xvT, *xhT, *faT, *fvT, *fhT;
    bf16 *Wap, *Wvp, *Wgavp, *Wgahp, *Wfavp, *Wfahp;
    bf16 *ghi1, *glo1, *ghi2, *glo2, *OmT1, *OmT2;
    cudaGetSymbolAddress((void**)&Ehi1,  d_Ehi1);
    cudaGetSymbolAddress((void**)&Elo1,  d_Elo1);
    cudaGetSymbolAddress((void**)&Ehi2,  d_Ehi2);
    cudaGetSymbolAddress((void**)&Elo2,  d_Elo2);
    cudaGetSymbolAddress((void**)&ps1,   d_ps1);
    cudaGetSymbolAddress((void**)&ps2,   d_ps2);
    cudaGetSymbolAddress((void**)&inv1,  d_inv1);
    cudaGetSymbolAddress((void**)&inv2,  d_inv2);
    cudaGetSymbolAddress((void**)&xT,    d_xT);
    cudaGetSymbolAddress((void**)&xvT,   d_xvT);
    cudaGetSymbolAddress((void**)&xhT,   d_xhT);
    cudaGetSymbolAddress((void**)&faT,   d_faT);
    cudaGetSymbolAddress((void**)&fvT,   d_fvT);
    cudaGetSymbolAddress((void**)&fhT,   d_fhT);
    cudaGetSymbolAddress((void**)&Wap,   d_Wap);
    cudaGetSymbolAddress((void**)&Wvp,   d_Wvp);
    cudaGetSymbolAddress((void**)&Wgavp, d_Wgavp);
    cudaGetSymbolAddress((void**)&Wgahp, d_Wgahp);
    cudaGetSymbolAddress((void**)&Wfavp, d_Wfavp);
    cudaGetSymbolAddress((void**)&Wfahp, d_Wfahp);
    cudaGetSymbolAddress((void**)&gav,   d_gav);
    cudaGetSymbolAddress((void**)&gah,   d_gah);
    cudaGetSymbolAddress((void**)&ghi1,  d_ghi1);
    cudaGetSymbolAddress((void**)&glo1,  d_glo1);
    cudaGetSymbolAddress((void**)&ghi2,  d_ghi2);
    cudaGetSymbolAddress((void**)&glo2,  d_glo2);
    cudaGetSymbolAddress((void**)&OmT1,  d_OmT1);
    cudaGetSymbolAddress((void**)&OmT2,  d_OmT2);

    const int SMEM_CV = 66560;
    const int SMEM_SC = 65536;
    const int SMEM_AP = 66048;
    const int SMEM_ST = 66048;
    cudaFuncSetAttribute(hmma_conv<0,0>, cudaFuncAttributeMaxDynamicSharedMemorySize, SMEM_CV);
    cudaFuncSetAttribute(hmma_conv<0,1>, cudaFuncAttributeMaxDynamicSharedMemorySize, SMEM_CV);
    cudaFuncSetAttribute(hmma_conv<1,0>, cudaFuncAttributeMaxDynamicSharedMemorySize, SMEM_CV);
    cudaFuncSetAttribute(hmma_conv<2,0>, cudaFuncAttributeMaxDynamicSharedMemorySize, SMEM_CV);
    cudaFuncSetAttribute(hmma_score,     cudaFuncAttributeMaxDynamicSharedMemorySize, SMEM_SC);
    cudaFuncSetAttribute(apply_fused,    cudaFuncAttributeMaxDynamicSharedMemorySize, SMEM_AP);
    cudaFuncSetAttribute(xsplitT,        cudaFuncAttributeMaxDynamicSharedMemorySize, SMEM_ST);

    const size_t sXT = (size_t)NN * K3C;
    const size_t sF  = (size_t)NN * K3F;
    const size_t sG  = (size_t)MD * NN;
    const size_t sX  = (size_t)CC * NN;
    const size_t halfOut = (size_t)BB * CC * NN;
    const float alpha = 0.08838834764831845f;  // 128^-0.5

    dim3 blk(256);
    dim3 gXT   (NN / 128, CC / 128, BB);
    dim3 gConv (NN / 128, 1, BB);
    dim3 gScore(NN / 128, NN / 128, BB);
    dim3 gApply(NN / 128, 1, BB);
    dim3 gOut  (NN / 128, CC / 128, BB);
    dim3 gInv  (NN / 256, 1, BB);
    dim3 gGs   ((MD * NN / 2) / 256, 1, BB);

    cudaStream_t s0 = 0, s1 = g_s1;

    // fork
    cudaEventRecord(g_evFork, s0);
    cudaStreamWaitEvent(s1, g_evFork, 0);

    // --- stream 0: x pack + faT/gah/gav convs ---
    xsplitT<<<gXT, blk, SMEM_ST, s0>>>(x, xT);
    wsplit<<<(MD * CC) / 256, blk, 0, s0>>>(Wa,   Wap,   CC);
    wsplit<<<(MD * CC) / 256, blk, 0, s0>>>(Wgah, Wgahp, CC);
    wsplit<<<(MD * CC) / 256, blk, 0, s0>>>(Wgav, Wgavp, CC);
    wsplit<<<(CC * MD) / 256, blk, 0, s0>>>(Wfah, Wfahp, MD);
    hmma_conv<0,1><<<gConv, blk, SMEM_CV, s0>>>(Wap, xT, sXT, K3C, nullptr, 0, faT, sF, ba, ga, ta, nullptr, 0);
    cudaEventRecord(g_evFA, s0);
    hmma_conv<1,0><<<gConv, blk, SMEM_CV, s0>>>(Wgahp, xT, sXT, K3C, gah, sG, nullptr, 0, bgah, nullptr, nullptr, nullptr, 0);
    hmma_conv<1,0><<<gConv, blk, SMEM_CV, s0>>>(Wgavp, xT, sXT, K3C, gav, sG, nullptr, 0, bgav, nullptr, nullptr, nullptr, 0);
    cudaEventRecord(g_evGAV, s0);

    // --- stream 1: x_h FIRST (fhT is on s0's critical path), then x_v ---
    xsplitT<<<gXT, blk, SMEM_ST, s1>>>(x_h, xhT);
    wsplit<<<(MD * CC) / 256, blk, 0, s1>>>(Wv, Wvp, CC);
    hmma_conv<0,0><<<gConv, blk, SMEM_CV, s1>>>(Wvp, xhT, sXT, K3C, nullptr, 0, fhT, sF, bv, gv, tv, nullptr, 0);
    cudaEventRecord(g_evFH, s1);
    xsplitT<<<gXT, blk, SMEM_ST, s1>>>(x_v, xvT);
    hmma_conv<0,0><<<gConv, blk, SMEM_CV, s1>>>(Wvp, xvT, sXT, K3C, nullptr, 0, fvT, sF, bv, gv, tv, nullptr, 0);
    wsplit<<<(CC * MD) / 256, blk, 0, s1>>>(Wfav, Wfavp, MD);

    // --- stream 0: pass ah (needs fhT from s1) ---
    cudaStreamWaitEvent(s0, g_evFH, 0);
    hmma_score<<<gScore, blk, SMEM_SC, s0>>>(faT, fhT, sF, Ehi1, Elo1, ps1, alpha);
    finalize_inv<<<gInv, blk, 0, s0>>>(ps1, inv1);
    gscale<<<gGs, blk, 0, s0>>>(gah, inv1, ghi1, glo1);
    apply_fused<<<gApply, blk, SMEM_AP, s0>>>(ghi1, glo1, Ehi1, Elo1, OmT1);
    hmma_conv<2,0><<<gOut, blk, SMEM_CV, s0>>>(Wfahp, OmT1, sF, K3F, out, sX, nullptr, 0, bfah, nullptr, nullptr, x, sX);

    // --- stream 1: pass av (needs faT + gav from s0) ---
    cudaStreamWaitEvent(s1, g_evFA, 0);
    hmma_score<<<gScore, blk, SMEM_SC, s1>>>(faT, fvT, sF, Ehi2, Elo2, ps2, alpha);
    finalize_inv<<<gInv, blk, 0, s1>>>(ps2, inv2);
    cudaStreamWaitEvent(s1, g_evGAV, 0);
    gscale<<<gGs, blk, 0, s1>>>(gav, inv2, ghi2, glo2);
    apply_fused<<<gApply, blk, SMEM_AP, s1>>>(ghi2, glo2, Ehi2, Elo2, OmT2);
    hmma_conv<2,0><<<gOut, blk, SMEM_CV, s1>>>(Wfavp, OmT2, sF, K3F, out + halfOut, sX, nullptr, 0, bfav, nullptr, nullptr, x, sX);

    // join
    cudaEventRecord(g_evEnd, s1);
    cudaStreamWaitEvent(s0, g_evEnd, 0);
}